// round 12
// baseline (speedup 1.0000x reference)
#include <cuda_runtime.h>
#include <math.h>

// R12 == R11 resubmitted: R11 failed on harness-side cudaErrorSystemNotReady
// ("system not yet initialized") before any kernel executed. No measurement
// of the R11 diff exists; re-benching it unchanged.

#define Bn   64
#define Nn   256
#define Mm   16
#define ONF  92
#define OEF  41
#define NF   128
#define EF   64
#define ROWS (Bn*Nn)   // 16384
#define NGRP (ROWS/8)  // 2048

typedef unsigned long long ull;

// ---- scratch ----
__device__ float g_nfA[ROWS*NF];
__device__ float g_nfB[ROWS*NF];
// interleaved pairs per node (512 floats):
//  [2o+0]=S_F(o) [2o+1]=S_C(o) ; [256+2o+0]=G_F(o) [256+2o+1]=G_C(o)
__device__ float g_SG[ROWS*512];
__device__ float g_efp[NGRP*OEF*128];  // GEMM-ready: [group][k][row], exact 41 k
__device__ ull   g_WceT[3*OEF*128];    // [l][k][o] = pack(WceF[o][k], WceC[o][k])
__device__ float g_bce[3*256];
__device__ float g_DA[Nn*Nn];
__device__ float g_fin[ROWS*EF];

__device__ __forceinline__ float tanh_ap(float x){
    float r; asm("tanh.approx.f32 %0, %1;" : "=f"(r) : "f"(x)); return r;
}
__device__ __forceinline__ float sigm(float x){
    return fmaf(tanh_ap(0.5f*x), 0.5f, 0.5f);
}
__device__ __forceinline__ float sigm_exact(float x){
    return __fdividef(1.f, 1.f + __expf(-x));
}
__device__ __forceinline__ float softplusf(float x){
    return fmaxf(x, 0.f) + __logf(1.f + __expf(-fabsf(x)));
}

__device__ __forceinline__ ull pack2(float lo, float hi){
    ull r; asm("mov.b64 %0, {%1, %2};" : "=l"(r) : "f"(lo), "f"(hi)); return r;
}
__device__ __forceinline__ void unpack2(ull v, float &lo, float &hi){
    asm("mov.b64 {%0, %1}, %2;" : "=f"(lo), "=f"(hi) : "l"(v));
}
__device__ __forceinline__ void fma2(ull &d, ull a, ull b){
    asm("fma.rn.f32x2 %0, %1, %2, %0;" : "+l"(d) : "l"(a), "l"(b));
}
__device__ __forceinline__ ull add2(ull a, ull b){
    ull r; asm("add.rn.f32x2 %0, %1, %2;" : "=l"(r) : "l"(a), "l"(b)); return r;
}

// ======== fused pre: ef transpose (exact 41k) + embed linear ========
#define PADB ((NGRP*OEF*128)/256)    // 41984
__global__ void pre_kernel(const float* __restrict__ ef,
                           const float* __restrict__ X, const float* __restrict__ W,
                           const float* __restrict__ bias, float* __restrict__ Y){
    __shared__ float Wsh[ONF*(NF+1)];
    __shared__ __align__(16) float Xsh[ONF*8];
    const int t = threadIdx.x;
    if (blockIdx.x < PADB){
        int i = blockIdx.x*256 + t;
        int group = i / (OEF*128);
        int rem   = i - group*(OEF*128);
        int k = rem >> 7, r = rem & 127;   // r = (node&7)*16 + m
        g_efp[i] = ef[((size_t)group*128 + r)*OEF + k];
        return;
    }
    const int rb = (blockIdx.x - PADB) * 8;
    for (int e = t; e < ONF*NF; e += 256){
        int o = e / ONF, k = e - o*ONF;
        Wsh[k*(NF+1) + o] = W[e];
    }
    for (int e = t; e < 8*ONF; e += 256){
        int r = e / ONF, k = e - r*ONF;
        Xsh[k*8 + r] = X[(size_t)(rb+r)*ONF + k];
    }
    __syncthreads();
    if (t < NF){
        float acc[8];
        #pragma unroll
        for (int r=0;r<8;r++) acc[r]=0.f;
        #pragma unroll 2
        for (int k=0;k<ONF;k++){
            float w = Wsh[k*(NF+1)+t];
            const float4* xr = (const float4*)(Xsh + k*8);
            float4 x0 = xr[0], x1 = xr[1];
            acc[0]+=x0.x*w; acc[1]+=x0.y*w; acc[2]+=x0.z*w; acc[3]+=x0.w*w;
            acc[4]+=x1.x*w; acc[5]+=x1.y*w; acc[6]+=x1.z*w; acc[7]+=x1.w*w;
        }
        float bv = bias[t];
        #pragma unroll
        for (int r=0;r<8;r++) Y[(size_t)(rb+r)*NF + t] = acc[r] + bv;
    }
}

// ======== wce2: g_WceT[l][k][o] (41 k rows) ; bce ========
__global__ void wce2_kernel(const float* __restrict__ W1,const float* __restrict__ W2,
                            const float* __restrict__ W3,const float* __restrict__ We,
                            const float* __restrict__ be){
    const int o = blockIdx.x;       // 0..127
    const int l = blockIdx.y;       // 0..2
    const int t = threadIdx.x;      // 0..47
    const float* W = (l==0)?W1:((l==1)?W2:W3);
    const float* rF = W + (size_t)o*320 + 256;
    const float* rC = W + (size_t)(o+128)*320 + 256;
    if (t < OEF){
        float aF = 0.f, aC = 0.f;
        for (int e=0;e<EF;e++){
            float v = We[e*OEF + t];
            aF += rF[e]*v; aC += rC[e]*v;
        }
        g_WceT[(l*OEF + t)*128 + o] = pack2(aF, aC);
    } else if (t == 44){
        float a = 0.f;
        for (int e=0;e<EF;e++) a += rF[e]*be[e];
        g_bce[l*256 + o] = a;
    } else if (t == 45){
        float a = 0.f;
        for (int e=0;e<EF;e++) a += rC[e]*be[e];
        g_bce[l*256 + o + 128] = a;
    }
}

__global__ void da_kernel(const float* __restrict__ dis,
                          const float* __restrict__ wp, const float* __restrict__ bp){
    int i = blockIdx.x*256 + threadIdx.x;
    g_DA[i] = sigm_exact(wp[0]*dis[i] + bp[0]);
}

// ======== SG GEMM: B dup moved to staging (no inner-loop packs) ========
__global__ __launch_bounds__(256,2)
void sg_kernel(const float* __restrict__ nf, const float* __restrict__ W,
               const float* __restrict__ bl, const float* __restrict__ bce){
    __shared__ float Ash[2][16][128];   // 16 KB
    __shared__ ull   Bsh[2][16][128];   // 32 KB (dup pairs)
    const int t  = threadIdx.x;
    const int rb = blockIdx.x * 128;
    const int cb = blockIdx.y * 128;
    const int tx = t & 15;
    const int ty = t >> 4;

    const int sr = t >> 1;
    const int sq = (t & 1) * 8;
    const float* Arow = nf + (size_t)(rb + sr)*NF + sq;
    const int ogc = cb + sr;
    const float* Brow = (ogc < 256) ? (W + ogc*320 + sq)
                                    : (W + (ogc-256)*320 + 128 + sq);

    float4 pa0 = *(const float4*)(Arow + 0);
    float4 pa1 = *(const float4*)(Arow + 4);
    float4 pb0 = *(const float4*)(Brow + 0);
    float4 pb1 = *(const float4*)(Brow + 4);

    ull acc[4][8];
    #pragma unroll
    for (int p=0;p<4;p++)
        #pragma unroll
        for (int j=0;j<8;j++) acc[p][j] = 0ULL;

    #pragma unroll 1
    for (int kt=0; kt<128; kt+=16){
        const int buf = (kt >> 4) & 1;
        Ash[buf][sq+0][sr]=pa0.x; Ash[buf][sq+1][sr]=pa0.y;
        Ash[buf][sq+2][sr]=pa0.z; Ash[buf][sq+3][sr]=pa0.w;
        Ash[buf][sq+4][sr]=pa1.x; Ash[buf][sq+5][sr]=pa1.y;
        Ash[buf][sq+6][sr]=pa1.z; Ash[buf][sq+7][sr]=pa1.w;
        Bsh[buf][sq+0][sr]=pack2(pb0.x,pb0.x); Bsh[buf][sq+1][sr]=pack2(pb0.y,pb0.y);
        Bsh[buf][sq+2][sr]=pack2(pb0.z,pb0.z); Bsh[buf][sq+3][sr]=pack2(pb0.w,pb0.w);
        Bsh[buf][sq+4][sr]=pack2(pb1.x,pb1.x); Bsh[buf][sq+5][sr]=pack2(pb1.y,pb1.y);
        Bsh[buf][sq+6][sr]=pack2(pb1.z,pb1.z); Bsh[buf][sq+7][sr]=pack2(pb1.w,pb1.w);
        __syncthreads();
        if (kt + 16 < 128){
            pa0 = *(const float4*)(Arow + kt + 16);
            pa1 = *(const float4*)(Arow + kt + 20);
            pb0 = *(const float4*)(Brow + kt + 16);
            pb1 = *(const float4*)(Brow + kt + 20);
        }
        #pragma unroll 8
        for (int k=0;k<16;k++){
            ulonglong2 a01 = *(const ulonglong2*)&Ash[buf][k][ty*8];
            ulonglong2 a23 = *(const ulonglong2*)&Ash[buf][k][ty*8+4];
            ulonglong2 b01 = *(const ulonglong2*)&Bsh[buf][k][tx*8];
            ulonglong2 b23 = *(const ulonglong2*)&Bsh[buf][k][tx*8+2];
            ulonglong2 b45 = *(const ulonglong2*)&Bsh[buf][k][tx*8+4];
            ulonglong2 b67 = *(const ulonglong2*)&Bsh[buf][k][tx*8+6];
            fma2(acc[0][0],a01.x,b01.x); fma2(acc[0][1],a01.x,b01.y);
            fma2(acc[0][2],a01.x,b23.x); fma2(acc[0][3],a01.x,b23.y);
            fma2(acc[0][4],a01.x,b45.x); fma2(acc[0][5],a01.x,b45.y);
            fma2(acc[0][6],a01.x,b67.x); fma2(acc[0][7],a01.x,b67.y);
            fma2(acc[1][0],a01.y,b01.x); fma2(acc[1][1],a01.y,b01.y);
            fma2(acc[1][2],a01.y,b23.x); fma2(acc[1][3],a01.y,b23.y);
            fma2(acc[1][4],a01.y,b45.x); fma2(acc[1][5],a01.y,b45.y);
            fma2(acc[1][6],a01.y,b67.x); fma2(acc[1][7],a01.y,b67.y);
            fma2(acc[2][0],a23.x,b01.x); fma2(acc[2][1],a23.x,b01.y);
            fma2(acc[2][2],a23.x,b23.x); fma2(acc[2][3],a23.x,b23.y);
            fma2(acc[2][4],a23.x,b45.x); fma2(acc[2][5],a23.x,b45.y);
            fma2(acc[2][6],a23.x,b67.x); fma2(acc[2][7],a23.x,b67.y);
            fma2(acc[3][0],a23.y,b01.x); fma2(acc[3][1],a23.y,b01.y);
            fma2(acc[3][2],a23.y,b23.x); fma2(acc[3][3],a23.y,b23.y);
            fma2(acc[3][4],a23.y,b45.x); fma2(acc[3][5],a23.y,b45.y);
            fma2(acc[3][6],a23.y,b67.x); fma2(acc[3][7],a23.y,b67.y);
        }
        __syncthreads();
    }
    #pragma unroll
    for (int j=0;j<8;j++){
        const int c = cb + tx*8 + j;
        const int aoff = (c & 256) + 2*(c & 127) + ((c >> 7) & 1);
        const float bias = (c < 256) ? (bl[c] + bce[c]) : 0.f;
        #pragma unroll
        for (int p=0;p<4;p++){
            float lo, hi; unpack2(acc[p][j], lo, hi);
            const int row = rb + ty*8 + 2*p;
            g_SG[(size_t)row*512 + aoff]     = lo + bias;
            g_SG[(size_t)(row+1)*512 + aoff] = hi + bias;
        }
    }
}

// ======== conv: 41-k edge-GEMM, coalesced dup staging ========
#define CONV_SMEM ((OEF*128 + OEF*64 + 8*64)*8 + 128*4)
__global__ __launch_bounds__(256,2)
void conv_kernel(const float* __restrict__ nf_in, float* __restrict__ nf_out,
                 const float* __restrict__ efpT, const int* __restrict__ eidx,
                 const ull* __restrict__ WceT, const float* __restrict__ alphap){
    extern __shared__ __align__(16) char smembuf[];
    ull*  A_sh   = (ull*)smembuf;           // [41][128] dup pairs
    ull*  B_sh   = A_sh + OEF*128;          // [41][64]
    ull*  sPp_sh = B_sh + OEF*64;           // [8][64]
    int*  idx_sh = (int*)(sPp_sh + 8*64);   // [128]
    const int t  = threadIdx.x;
    const int tx = t & 15;
    const int ty = t >> 4;
    const int group = blockIdx.x >> 1;
    const int H = blockIdx.x & 1;
    const int node0 = group * 8;

    // stage A dup: float2 source unit -> one STS.128 at consecutive 16B
    {
        const float2* src = (const float2*)(efpT + (size_t)group*(OEF*128));
        ulonglong2* dst = (ulonglong2*)A_sh;
        #pragma unroll
        for (int p=0;p<11;p++){
            int e = t + p*256;               // 2624 float2 units
            if (e < (OEF*128)/2){
                float2 v = src[e];
                ulonglong2 d;
                d.x = pack2(v.x, v.x);
                d.y = pack2(v.y, v.y);
                dst[e] = d;
            }
        }
    }
    // stage B: 41 k x 64 o-pairs
    {
        #pragma unroll
        for (int p=0;p<11;p++){
            int e = t + p*256;               // 2624
            if (e < OEF*64){
                int k = e >> 6, op = e & 63;
                B_sh[e] = WceT[k*128 + H*64 + op];
            }
        }
    }
    // stage S-pairs
    {
        #pragma unroll
        for (int p=0;p<2;p++){
            int e = t + p*256;
            int nl = e >> 6, op = e & 63;
            sPp_sh[e] = *(const ull*)(g_SG + (size_t)(node0+nl)*512 + 2*(H*64+op));
        }
    }
    if (t < 128) idx_sh[t] = eidx[node0*Mm + t];
    __syncthreads();

    ull acc[8][4];
    #pragma unroll
    for (int i=0;i<8;i++)
        #pragma unroll
        for (int q=0;q<4;q++) acc[i][q] = 0ULL;

    #pragma unroll 4
    for (int k=0;k<OEF;k++){
        const ull* Ak = A_sh + k*128 + ty*8;
        const ull* Bk = B_sh + k*64 + tx*4;
        ulonglong2 a01 = *(const ulonglong2*)Ak;
        ulonglong2 a23 = *(const ulonglong2*)(Ak+2);
        ulonglong2 a45 = *(const ulonglong2*)(Ak+4);
        ulonglong2 a67 = *(const ulonglong2*)(Ak+6);
        ulonglong2 b01 = *(const ulonglong2*)Bk;
        ulonglong2 b23 = *(const ulonglong2*)(Bk+2);
        fma2(acc[0][0],a01.x,b01.x); fma2(acc[0][1],a01.x,b01.y);
        fma2(acc[0][2],a01.x,b23.x); fma2(acc[0][3],a01.x,b23.y);
        fma2(acc[1][0],a01.y,b01.x); fma2(acc[1][1],a01.y,b01.y);
        fma2(acc[1][2],a01.y,b23.x); fma2(acc[1][3],a01.y,b23.y);
        fma2(acc[2][0],a23.x,b01.x); fma2(acc[2][1],a23.x,b01.y);
        fma2(acc[2][2],a23.x,b23.x); fma2(acc[2][3],a23.x,b23.y);
        fma2(acc[3][0],a23.y,b01.x); fma2(acc[3][1],a23.y,b01.y);
        fma2(acc[3][2],a23.y,b23.x); fma2(acc[3][3],a23.y,b23.y);
        fma2(acc[4][0],a45.x,b01.x); fma2(acc[4][1],a45.x,b01.y);
        fma2(acc[4][2],a45.x,b23.x); fma2(acc[4][3],a45.x,b23.y);
        fma2(acc[5][0],a45.y,b01.x); fma2(acc[5][1],a45.y,b01.y);
        fma2(acc[5][2],a45.y,b23.x); fma2(acc[5][3],a45.y,b23.y);
        fma2(acc[6][0],a67.x,b01.x); fma2(acc[6][1],a67.x,b01.y);
        fma2(acc[6][2],a67.x,b23.x); fma2(acc[6][3],a67.x,b23.y);
        fma2(acc[7][0],a67.y,b01.x); fma2(acc[7][1],a67.y,b01.y);
        fma2(acc[7][2],a67.y,b23.x); fma2(acc[7][3],a67.y,b23.y);
    }

    // epilogue
    const int nl   = ty >> 1;
    const int node = node0 + nl;
    const int m0   = (ty & 1) * 8;
    const int bb   = node >> 8;
    const float* SGb = g_SG + (size_t)bb*Nn*512 + 256 + 2*(H*64);
    const ull sp0 = sPp_sh[nl*64 + tx*4 + 0];
    const ull sp1 = sPp_sh[nl*64 + tx*4 + 1];
    const ull sp2 = sPp_sh[nl*64 + tx*4 + 2];
    const ull sp3 = sPp_sh[nl*64 + tx*4 + 3];
    float part0=0.f, part1=0.f, part2=0.f, part3=0.f;
    #pragma unroll
    for (int i=0;i<8;i++){
        const int j  = idx_sh[nl*Mm + m0 + i];
        const int jc = (j < 0) ? 0 : j;
        const ull* Gp = (const ull*)(SGb + (size_t)jc*512) + tx*4;
        ulonglong2 g01 = *(const ulonglong2*)Gp;
        ulonglong2 g23 = *((const ulonglong2*)Gp + 1);
        ull v0 = add2(add2(acc[i][0], sp0), g01.x);
        ull v1 = add2(add2(acc[i][1], sp1), g01.y);
        ull v2 = add2(add2(acc[i][2], sp2), g23.x);
        ull v3 = add2(add2(acc[i][3], sp3), g23.y);
        float f,c;
        const float msk = (j >= 0) ? 1.f : 0.f;
        unpack2(v0,f,c); part0 += msk*sigm(f)*softplusf(c);
        unpack2(v1,f,c); part1 += msk*sigm(f)*softplusf(c);
        unpack2(v2,f,c); part2 += msk*sigm(f)*softplusf(c);
        unpack2(v3,f,c); part3 += msk*sigm(f)*softplusf(c);
    }
    const float tt0 = part0 + __shfl_xor_sync(0xFFFFFFFFu, part0, 16);
    const float tt1 = part1 + __shfl_xor_sync(0xFFFFFFFFu, part1, 16);
    const float tt2 = part2 + __shfl_xor_sync(0xFFFFFFFFu, part2, 16);
    const float tt3 = part3 + __shfl_xor_sync(0xFFFFFFFFu, part3, 16);
    if ((ty & 1) == 0){
        const float alpha = alphap[0];
        const size_t off = (size_t)node*NF + H*64 + tx*4;
        const float4 sv = *(const float4*)(nf_in + off);
        float4 o4;
        o4.x = softplusf(fmaf(alpha, sv.x, tt0));
        o4.y = softplusf(fmaf(alpha, sv.y, tt1));
        o4.z = softplusf(fmaf(alpha, sv.z, tt2));
        o4.w = softplusf(fmaf(alpha, sv.w, tt3));
        *(float4*)(nf_out + off) = o4;
    }
}

// ---------------- final linear ----------------
template<int IN,int OUT,int RPB>
__global__ void linear_kernel(const float* __restrict__ X, const float* __restrict__ W,
                              const float* __restrict__ bias, float* __restrict__ Y){
    __shared__ float Wsh[IN*(OUT+1)];
    __shared__ __align__(16) float Xsh[IN*RPB];
    const int rb = blockIdx.x * RPB;
    const int t  = threadIdx.x;
    for (int e = t; e < IN*OUT; e += OUT){
        int o = e / IN, k = e - o*IN;
        Wsh[k*(OUT+1) + o] = W[e];
    }
    for (int e = t; e < RPB*IN; e += OUT){
        int r = e / IN, k = e - r*IN;
        Xsh[k*RPB + r] = X[(size_t)(rb+r)*IN + k];
    }
    __syncthreads();
    float acc[RPB];
    #pragma unroll
    for (int r=0;r<RPB;r++) acc[r]=0.f;
    #pragma unroll 2
    for (int k=0;k<IN;k++){
        float w = Wsh[k*(OUT+1)+t];
        const float4* xr = (const float4*)(Xsh + k*RPB);
        #pragma unroll
        for (int r4=0;r4<RPB/4;r4++){
            float4 xv = xr[r4];
            acc[4*r4+0] += xv.x*w; acc[4*r4+1] += xv.y*w;
            acc[4*r4+2] += xv.z*w; acc[4*r4+3] += xv.w*w;
        }
    }
    float bv = bias[t];
    #pragma unroll
    for (int r=0;r<RPB;r++) Y[(size_t)(rb+r)*OUT + t] = acc[r] + bv;
}

// -------- output --------
__global__ void out_kernel(float* __restrict__ out){
    __shared__ float DS[32*33];
    __shared__ float NS[32*65];
    const int t  = threadIdx.x;
    const int it = blockIdx.x;
    const int b  = blockIdx.y;
    const int i_l = t & 31;
    const int fg  = t >> 5;
    float acc[8];
    #pragma unroll
    for (int f=0;f<8;f++) acc[f]=0.f;

    for (int jt=0; jt<8; jt++){
        #pragma unroll
        for (int i=0;i<4;i++){
            int e = t + i*256; int r = e>>5; int c = e&31;
            DS[r*33+c] = g_DA[(it*32+r)*Nn + jt*32 + c];
        }
        #pragma unroll
        for (int i=0;i<8;i++){
            int e = t + i*256; int j = e>>6; int f = e&63;
            NS[j*65+f] = g_fin[(b*Nn + jt*32 + j)*EF + f];
        }
        __syncthreads();
        #pragma unroll
        for (int j=0;j<32;j++){
            float d = DS[i_l*33 + j];
            #pragma unroll
            for (int f=0;f<8;f++) acc[f] += d * NS[j*65 + fg*8 + f];
        }
        __syncthreads();
    }
    const int i = it*32 + i_l;
    float* orow = out + (size_t)(b*Nn + i)*128;
    #pragma unroll
    for (int f=0;f<8;f++) orow[64 + fg*8 + f] = acc[f];
    for (int e=t; e<32*64; e+=256){
        int r = e>>6; int f = e&63;
        out[(size_t)(b*Nn + it*32 + r)*128 + f] = g_fin[(b*Nn + it*32 + r)*EF + f];
    }
}

extern "C" void kernel_launch(void* const* d_in, const int* in_sizes, int n_in,
                              void* d_out, int out_size){
    const float* node_fea = (const float*)d_in[0];
    const float* edge_fea = (const float*)d_in[1];
    const int*   eidx     = (const int*)  d_in[2];
    const float* dis      = (const float*)d_in[3];
    const float* Wn  = (const float*)d_in[4];
    const float* bn  = (const float*)d_in[5];
    const float* We  = (const float*)d_in[6];
    const float* be  = (const float*)d_in[7];
    const float* W1  = (const float*)d_in[8];
    const float* b1  = (const float*)d_in[9];
    const float* a1  = (const float*)d_in[10];
    const float* W2  = (const float*)d_in[11];
    const float* b2  = (const float*)d_in[12];
    const float* a2  = (const float*)d_in[13];
    const float* W3  = (const float*)d_in[14];
    const float* b3  = (const float*)d_in[15];
    const float* a3  = (const float*)d_in[16];
    const float* Wf  = (const float*)d_in[17];
    const float* bf  = (const float*)d_in[18];
    const float* DAw = (const float*)d_in[19];
    const float* DAb = (const float*)d_in[20];
    float* out = (float*)d_out;

    float *nfA, *nfB, *bceP, *finP, *efpP;
    ull *WceTP;
    cudaGetSymbolAddress((void**)&nfA,   g_nfA);
    cudaGetSymbolAddress((void**)&nfB,   g_nfB);
    cudaGetSymbolAddress((void**)&bceP,  g_bce);
    cudaGetSymbolAddress((void**)&WceTP, g_WceT);
    cudaGetSymbolAddress((void**)&finP,  g_fin);
    cudaGetSymbolAddress((void**)&efpP,  g_efp);

    cudaFuncSetAttribute(conv_kernel,
                         cudaFuncAttributeMaxDynamicSharedMemorySize, CONV_SMEM);

    const float* Ws[3] = {W1,W2,W3};
    const float* bs[3] = {b1,b2,b3};
    const float* as[3] = {a1,a2,a3};

    // launches: pre(1), wce2(2), sg1(3), conv1(4 = profiled)
    pre_kernel<<<PADB + ROWS/8, 256>>>(edge_fea, node_fea, Wn, bn, nfA);
    wce2_kernel<<<dim3(128,3), 48>>>(W1, W2, W3, We, be);

    float* nin  = nfA;
    float* nout = nfB;
    for (int l=0; l<3; l++){
        sg_kernel<<<dim3(ROWS/128, 4), 256>>>(nin, Ws[l], bs[l], bceP + l*256);
        conv_kernel<<<NGRP*2, 256, CONV_SMEM>>>(nin, nout, efpP, eidx,
                                                WceTP + (size_t)l*OEF*128, as[l]);
        float* tmp = nin; nin = nout; nout = tmp;
    }

    da_kernel<<<256, 256>>>(dis, DAw, DAb);
    linear_kernel<NF,EF,16><<<ROWS/16, EF>>>(nin, Wf, bf, finP);
    out_kernel<<<dim3(8, Bn), 256>>>(out);
}

// round 13
// speedup vs baseline: 1.0006x; 1.0006x over previous
#include <cuda_runtime.h>
#include <math.h>

// R12 == R11 resubmitted: R11 failed on harness-side cudaErrorSystemNotReady
// ("system not yet initialized") before any kernel executed. No measurement
// of the R11 diff exists; re-benching it unchanged.

#define Bn   64
#define Nn   256
#define Mm   16
#define ONF  92
#define OEF  41
#define NF   128
#define EF   64
#define ROWS (Bn*Nn)   // 16384
#define NGRP (ROWS/8)  // 2048

typedef unsigned long long ull;

// ---- scratch ----
__device__ float g_nfA[ROWS*NF];
__device__ float g_nfB[ROWS*NF];
// interleaved pairs per node (512 floats):
//  [2o+0]=S_F(o) [2o+1]=S_C(o) ; [256+2o+0]=G_F(o) [256+2o+1]=G_C(o)
__device__ float g_SG[ROWS*512];
__device__ float g_efp[NGRP*OEF*128];  // GEMM-ready: [group][k][row], exact 41 k
__device__ ull   g_WceT[3*OEF*128];    // [l][k][o] = pack(WceF[o][k], WceC[o][k])
__device__ float g_bce[3*256];
__device__ float g_DA[Nn*Nn];
__device__ float g_fin[ROWS*EF];

__device__ __forceinline__ float tanh_ap(float x){
    float r; asm("tanh.approx.f32 %0, %1;" : "=f"(r) : "f"(x)); return r;
}
__device__ __forceinline__ float sigm(float x){
    return fmaf(tanh_ap(0.5f*x), 0.5f, 0.5f);
}
__device__ __forceinline__ float sigm_exact(float x){
    return __fdividef(1.f, 1.f + __expf(-x));
}
__device__ __forceinline__ float softplusf(float x){
    return fmaxf(x, 0.f) + __logf(1.f + __expf(-fabsf(x)));
}

__device__ __forceinline__ ull pack2(float lo, float hi){
    ull r; asm("mov.b64 %0, {%1, %2};" : "=l"(r) : "f"(lo), "f"(hi)); return r;
}
__device__ __forceinline__ void unpack2(ull v, float &lo, float &hi){
    asm("mov.b64 {%0, %1}, %2;" : "=f"(lo), "=f"(hi) : "l"(v));
}
__device__ __forceinline__ void fma2(ull &d, ull a, ull b){
    asm("fma.rn.f32x2 %0, %1, %2, %0;" : "+l"(d) : "l"(a), "l"(b));
}
__device__ __forceinline__ ull add2(ull a, ull b){
    ull r; asm("add.rn.f32x2 %0, %1, %2;" : "=l"(r) : "l"(a), "l"(b)); return r;
}

// ======== fused pre: ef transpose (exact 41k) + embed linear ========
#define PADB ((NGRP*OEF*128)/256)    // 41984
__global__ void pre_kernel(const float* __restrict__ ef,
                           const float* __restrict__ X, const float* __restrict__ W,
                           const float* __restrict__ bias, float* __restrict__ Y){
    __shared__ float Wsh[ONF*(NF+1)];
    __shared__ __align__(16) float Xsh[ONF*8];
    const int t = threadIdx.x;
    if (blockIdx.x < PADB){
        int i = blockIdx.x*256 + t;
        int group = i / (OEF*128);
        int rem   = i - group*(OEF*128);
        int k = rem >> 7, r = rem & 127;   // r = (node&7)*16 + m
        g_efp[i] = ef[((size_t)group*128 + r)*OEF + k];
        return;
    }
    const int rb = (blockIdx.x - PADB) * 8;
    for (int e = t; e < ONF*NF; e += 256){
        int o = e / ONF, k = e - o*ONF;
        Wsh[k*(NF+1) + o] = W[e];
    }
    for (int e = t; e < 8*ONF; e += 256){
        int r = e / ONF, k = e - r*ONF;
        Xsh[k*8 + r] = X[(size_t)(rb+r)*ONF + k];
    }
    __syncthreads();
    if (t < NF){
        float acc[8];
        #pragma unroll
        for (int r=0;r<8;r++) acc[r]=0.f;
        #pragma unroll 2
        for (int k=0;k<ONF;k++){
            float w = Wsh[k*(NF+1)+t];
            const float4* xr = (const float4*)(Xsh + k*8);
            float4 x0 = xr[0], x1 = xr[1];
            acc[0]+=x0.x*w; acc[1]+=x0.y*w; acc[2]+=x0.z*w; acc[3]+=x0.w*w;
            acc[4]+=x1.x*w; acc[5]+=x1.y*w; acc[6]+=x1.z*w; acc[7]+=x1.w*w;
        }
        float bv = bias[t];
        #pragma unroll
        for (int r=0;r<8;r++) Y[(size_t)(rb+r)*NF + t] = acc[r] + bv;
    }
}

// ======== wce2: g_WceT[l][k][o] (41 k rows) ; bce ========
__global__ void wce2_kernel(const float* __restrict__ W1,const float* __restrict__ W2,
                            const float* __restrict__ W3,const float* __restrict__ We,
                            const float* __restrict__ be){
    const int o = blockIdx.x;       // 0..127
    const int l = blockIdx.y;       // 0..2
    const int t = threadIdx.x;      // 0..47
    const float* W = (l==0)?W1:((l==1)?W2:W3);
    const float* rF = W + (size_t)o*320 + 256;
    const float* rC = W + (size_t)(o+128)*320 + 256;
    if (t < OEF){
        float aF = 0.f, aC = 0.f;
        for (int e=0;e<EF;e++){
            float v = We[e*OEF + t];
            aF += rF[e]*v; aC += rC[e]*v;
        }
        g_WceT[(l*OEF + t)*128 + o] = pack2(aF, aC);
    } else if (t == 44){
        float a = 0.f;
        for (int e=0;e<EF;e++) a += rF[e]*be[e];
        g_bce[l*256 + o] = a;
    } else if (t == 45){
        float a = 0.f;
        for (int e=0;e<EF;e++) a += rC[e]*be[e];
        g_bce[l*256 + o + 128] = a;
    }
}

__global__ void da_kernel(const float* __restrict__ dis,
                          const float* __restrict__ wp, const float* __restrict__ bp){
    int i = blockIdx.x*256 + threadIdx.x;
    g_DA[i] = sigm_exact(wp[0]*dis[i] + bp[0]);
}

// ======== SG GEMM: B dup moved to staging (no inner-loop packs) ========
__global__ __launch_bounds__(256,2)
void sg_kernel(const float* __restrict__ nf, const float* __restrict__ W,
               const float* __restrict__ bl, const float* __restrict__ bce){
    __shared__ float Ash[2][16][128];   // 16 KB
    __shared__ ull   Bsh[2][16][128];   // 32 KB (dup pairs)
    const int t  = threadIdx.x;
    const int rb = blockIdx.x * 128;
    const int cb = blockIdx.y * 128;
    const int tx = t & 15;
    const int ty = t >> 4;

    const int sr = t >> 1;
    const int sq = (t & 1) * 8;
    const float* Arow = nf + (size_t)(rb + sr)*NF + sq;
    const int ogc = cb + sr;
    const float* Brow = (ogc < 256) ? (W + ogc*320 + sq)
                                    : (W + (ogc-256)*320 + 128 + sq);

    float4 pa0 = *(const float4*)(Arow + 0);
    float4 pa1 = *(const float4*)(Arow + 4);
    float4 pb0 = *(const float4*)(Brow + 0);
    float4 pb1 = *(const float4*)(Brow + 4);

    ull acc[4][8];
    #pragma unroll
    for (int p=0;p<4;p++)
        #pragma unroll
        for (int j=0;j<8;j++) acc[p][j] = 0ULL;

    #pragma unroll 1
    for (int kt=0; kt<128; kt+=16){
        const int buf = (kt >> 4) & 1;
        Ash[buf][sq+0][sr]=pa0.x; Ash[buf][sq+1][sr]=pa0.y;
        Ash[buf][sq+2][sr]=pa0.z; Ash[buf][sq+3][sr]=pa0.w;
        Ash[buf][sq+4][sr]=pa1.x; Ash[buf][sq+5][sr]=pa1.y;
        Ash[buf][sq+6][sr]=pa1.z; Ash[buf][sq+7][sr]=pa1.w;
        Bsh[buf][sq+0][sr]=pack2(pb0.x,pb0.x); Bsh[buf][sq+1][sr]=pack2(pb0.y,pb0.y);
        Bsh[buf][sq+2][sr]=pack2(pb0.z,pb0.z); Bsh[buf][sq+3][sr]=pack2(pb0.w,pb0.w);
        Bsh[buf][sq+4][sr]=pack2(pb1.x,pb1.x); Bsh[buf][sq+5][sr]=pack2(pb1.y,pb1.y);
        Bsh[buf][sq+6][sr]=pack2(pb1.z,pb1.z); Bsh[buf][sq+7][sr]=pack2(pb1.w,pb1.w);
        __syncthreads();
        if (kt + 16 < 128){
            pa0 = *(const float4*)(Arow + kt + 16);
            pa1 = *(const float4*)(Arow + kt + 20);
            pb0 = *(const float4*)(Brow + kt + 16);
            pb1 = *(const float4*)(Brow + kt + 20);
        }
        #pragma unroll 8
        for (int k=0;k<16;k++){
            ulonglong2 a01 = *(const ulonglong2*)&Ash[buf][k][ty*8];
            ulonglong2 a23 = *(const ulonglong2*)&Ash[buf][k][ty*8+4];
            ulonglong2 b01 = *(const ulonglong2*)&Bsh[buf][k][tx*8];
            ulonglong2 b23 = *(const ulonglong2*)&Bsh[buf][k][tx*8+2];
            ulonglong2 b45 = *(const ulonglong2*)&Bsh[buf][k][tx*8+4];
            ulonglong2 b67 = *(const ulonglong2*)&Bsh[buf][k][tx*8+6];
            fma2(acc[0][0],a01.x,b01.x); fma2(acc[0][1],a01.x,b01.y);
            fma2(acc[0][2],a01.x,b23.x); fma2(acc[0][3],a01.x,b23.y);
            fma2(acc[0][4],a01.x,b45.x); fma2(acc[0][5],a01.x,b45.y);
            fma2(acc[0][6],a01.x,b67.x); fma2(acc[0][7],a01.x,b67.y);
            fma2(acc[1][0],a01.y,b01.x); fma2(acc[1][1],a01.y,b01.y);
            fma2(acc[1][2],a01.y,b23.x); fma2(acc[1][3],a01.y,b23.y);
            fma2(acc[1][4],a01.y,b45.x); fma2(acc[1][5],a01.y,b45.y);
            fma2(acc[1][6],a01.y,b67.x); fma2(acc[1][7],a01.y,b67.y);
            fma2(acc[2][0],a23.x,b01.x); fma2(acc[2][1],a23.x,b01.y);
            fma2(acc[2][2],a23.x,b23.x); fma2(acc[2][3],a23.x,b23.y);
            fma2(acc[2][4],a23.x,b45.x); fma2(acc[2][5],a23.x,b45.y);
            fma2(acc[2][6],a23.x,b67.x); fma2(acc[2][7],a23.x,b67.y);
            fma2(acc[3][0],a23.y,b01.x); fma2(acc[3][1],a23.y,b01.y);
            fma2(acc[3][2],a23.y,b23.x); fma2(acc[3][3],a23.y,b23.y);
            fma2(acc[3][4],a23.y,b45.x); fma2(acc[3][5],a23.y,b45.y);
            fma2(acc[3][6],a23.y,b67.x); fma2(acc[3][7],a23.y,b67.y);
        }
        __syncthreads();
    }
    #pragma unroll
    for (int j=0;j<8;j++){
        const int c = cb + tx*8 + j;
        const int aoff = (c & 256) + 2*(c & 127) + ((c >> 7) & 1);
        const float bias = (c < 256) ? (bl[c] + bce[c]) : 0.f;
        #pragma unroll
        for (int p=0;p<4;p++){
            float lo, hi; unpack2(acc[p][j], lo, hi);
            const int row = rb + ty*8 + 2*p;
            g_SG[(size_t)row*512 + aoff]     = lo + bias;
            g_SG[(size_t)(row+1)*512 + aoff] = hi + bias;
        }
    }
}

// ======== conv: 41-k edge-GEMM, coalesced dup staging ========
#define CONV_SMEM ((OEF*128 + OEF*64 + 8*64)*8 + 128*4)
__global__ __launch_bounds__(256,2)
void conv_kernel(const float* __restrict__ nf_in, float* __restrict__ nf_out,
                 const float* __restrict__ efpT, const int* __restrict__ eidx,
                 const ull* __restrict__ WceT, const float* __restrict__ alphap){
    extern __shared__ __align__(16) char smembuf[];
    ull*  A_sh   = (ull*)smembuf;           // [41][128] dup pairs
    ull*  B_sh   = A_sh + OEF*128;          // [41][64]
    ull*  sPp_sh = B_sh + OEF*64;           // [8][64]
    int*  idx_sh = (int*)(sPp_sh + 8*64);   // [128]
    const int t  = threadIdx.x;
    const int tx = t & 15;
    const int ty = t >> 4;
    const int group = blockIdx.x >> 1;
    const int H = blockIdx.x & 1;
    const int node0 = group * 8;

    // stage A dup: float2 source unit -> one STS.128 at consecutive 16B
    {
        const float2* src = (const float2*)(efpT + (size_t)group*(OEF*128));
        ulonglong2* dst = (ulonglong2*)A_sh;
        #pragma unroll
        for (int p=0;p<11;p++){
            int e = t + p*256;               // 2624 float2 units
            if (e < (OEF*128)/2){
                float2 v = src[e];
                ulonglong2 d;
                d.x = pack2(v.x, v.x);
                d.y = pack2(v.y, v.y);
                dst[e] = d;
            }
        }
    }
    // stage B: 41 k x 64 o-pairs
    {
        #pragma unroll
        for (int p=0;p<11;p++){
            int e = t + p*256;               // 2624
            if (e < OEF*64){
                int k = e >> 6, op = e & 63;
                B_sh[e] = WceT[k*128 + H*64 + op];
            }
        }
    }
    // stage S-pairs
    {
        #pragma unroll
        for (int p=0;p<2;p++){
            int e = t + p*256;
            int nl = e >> 6, op = e & 63;
            sPp_sh[e] = *(const ull*)(g_SG + (size_t)(node0+nl)*512 + 2*(H*64+op));
        }
    }
    if (t < 128) idx_sh[t] = eidx[node0*Mm + t];
    __syncthreads();

    ull acc[8][4];
    #pragma unroll
    for (int i=0;i<8;i++)
        #pragma unroll
        for (int q=0;q<4;q++) acc[i][q] = 0ULL;

    #pragma unroll 4
    for (int k=0;k<OEF;k++){
        const ull* Ak = A_sh + k*128 + ty*8;
        const ull* Bk = B_sh + k*64 + tx*4;
        ulonglong2 a01 = *(const ulonglong2*)Ak;
        ulonglong2 a23 = *(const ulonglong2*)(Ak+2);
        ulonglong2 a45 = *(const ulonglong2*)(Ak+4);
        ulonglong2 a67 = *(const ulonglong2*)(Ak+6);
        ulonglong2 b01 = *(const ulonglong2*)Bk;
        ulonglong2 b23 = *(const ulonglong2*)(Bk+2);
        fma2(acc[0][0],a01.x,b01.x); fma2(acc[0][1],a01.x,b01.y);
        fma2(acc[0][2],a01.x,b23.x); fma2(acc[0][3],a01.x,b23.y);
        fma2(acc[1][0],a01.y,b01.x); fma2(acc[1][1],a01.y,b01.y);
        fma2(acc[1][2],a01.y,b23.x); fma2(acc[1][3],a01.y,b23.y);
        fma2(acc[2][0],a23.x,b01.x); fma2(acc[2][1],a23.x,b01.y);
        fma2(acc[2][2],a23.x,b23.x); fma2(acc[2][3],a23.x,b23.y);
        fma2(acc[3][0],a23.y,b01.x); fma2(acc[3][1],a23.y,b01.y);
        fma2(acc[3][2],a23.y,b23.x); fma2(acc[3][3],a23.y,b23.y);
        fma2(acc[4][0],a45.x,b01.x); fma2(acc[4][1],a45.x,b01.y);
        fma2(acc[4][2],a45.x,b23.x); fma2(acc[4][3],a45.x,b23.y);
        fma2(acc[5][0],a45.y,b01.x); fma2(acc[5][1],a45.y,b01.y);
        fma2(acc[5][2],a45.y,b23.x); fma2(acc[5][3],a45.y,b23.y);
        fma2(acc[6][0],a67.x,b01.x); fma2(acc[6][1],a67.x,b01.y);
        fma2(acc[6][2],a67.x,b23.x); fma2(acc[6][3],a67.x,b23.y);
        fma2(acc[7][0],a67.y,b01.x); fma2(acc[7][1],a67.y,b01.y);
        fma2(acc[7][2],a67.y,b23.x); fma2(acc[7][3],a67.y,b23.y);
    }

    // epilogue
    const int nl   = ty >> 1;
    const int node = node0 + nl;
    const int m0   = (ty & 1) * 8;
    const int bb   = node >> 8;
    const float* SGb = g_SG + (size_t)bb*Nn*512 + 256 + 2*(H*64);
    const ull sp0 = sPp_sh[nl*64 + tx*4 + 0];
    const ull sp1 = sPp_sh[nl*64 + tx*4 + 1];
    const ull sp2 = sPp_sh[nl*64 + tx*4 + 2];
    const ull sp3 = sPp_sh[nl*64 + tx*4 + 3];
    float part0=0.f, part1=0.f, part2=0.f, part3=0.f;
    #pragma unroll
    for (int i=0;i<8;i++){
        const int j  = idx_sh[nl*Mm + m0 + i];
        const int jc = (j < 0) ? 0 : j;
        const ull* Gp = (const ull*)(SGb + (size_t)jc*512) + tx*4;
        ulonglong2 g01 = *(const ulonglong2*)Gp;
        ulonglong2 g23 = *((const ulonglong2*)Gp + 1);
        ull v0 = add2(add2(acc[i][0], sp0), g01.x);
        ull v1 = add2(add2(acc[i][1], sp1), g01.y);
        ull v2 = add2(add2(acc[i][2], sp2), g23.x);
        ull v3 = add2(add2(acc[i][3], sp3), g23.y);
        float f,c;
        const float msk = (j >= 0) ? 1.f : 0.f;
        unpack2(v0,f,c); part0 += msk*sigm(f)*softplusf(c);
        unpack2(v1,f,c); part1 += msk*sigm(f)*softplusf(c);
        unpack2(v2,f,c); part2 += msk*sigm(f)*softplusf(c);
        unpack2(v3,f,c); part3 += msk*sigm(f)*softplusf(c);
    }
    const float tt0 = part0 + __shfl_xor_sync(0xFFFFFFFFu, part0, 16);
    const float tt1 = part1 + __shfl_xor_sync(0xFFFFFFFFu, part1, 16);
    const float tt2 = part2 + __shfl_xor_sync(0xFFFFFFFFu, part2, 16);
    const float tt3 = part3 + __shfl_xor_sync(0xFFFFFFFFu, part3, 16);
    if ((ty & 1) == 0){
        const float alpha = alphap[0];
        const size_t off = (size_t)node*NF + H*64 + tx*4;
        const float4 sv = *(const float4*)(nf_in + off);
        float4 o4;
        o4.x = softplusf(fmaf(alpha, sv.x, tt0));
        o4.y = softplusf(fmaf(alpha, sv.y, tt1));
        o4.z = softplusf(fmaf(alpha, sv.z, tt2));
        o4.w = softplusf(fmaf(alpha, sv.w, tt3));
        *(float4*)(nf_out + off) = o4;
    }
}

// ---------------- final linear ----------------
template<int IN,int OUT,int RPB>
__global__ void linear_kernel(const float* __restrict__ X, const float* __restrict__ W,
                              const float* __restrict__ bias, float* __restrict__ Y){
    __shared__ float Wsh[IN*(OUT+1)];
    __shared__ __align__(16) float Xsh[IN*RPB];
    const int rb = blockIdx.x * RPB;
    const int t  = threadIdx.x;
    for (int e = t; e < IN*OUT; e += OUT){
        int o = e / IN, k = e - o*IN;
        Wsh[k*(OUT+1) + o] = W[e];
    }
    for (int e = t; e < RPB*IN; e += OUT){
        int r = e / IN, k = e - r*IN;
        Xsh[k*RPB + r] = X[(size_t)(rb+r)*IN + k];
    }
    __syncthreads();
    float acc[RPB];
    #pragma unroll
    for (int r=0;r<RPB;r++) acc[r]=0.f;
    #pragma unroll 2
    for (int k=0;k<IN;k++){
        float w = Wsh[k*(OUT+1)+t];
        const float4* xr = (const float4*)(Xsh + k*RPB);
        #pragma unroll
        for (int r4=0;r4<RPB/4;r4++){
            float4 xv = xr[r4];
            acc[4*r4+0] += xv.x*w; acc[4*r4+1] += xv.y*w;
            acc[4*r4+2] += xv.z*w; acc[4*r4+3] += xv.w*w;
        }
    }
    float bv = bias[t];
    #pragma unroll
    for (int r=0;r<RPB;r++) Y[(size_t)(rb+r)*OUT + t] = acc[r] + bv;
}

// -------- output --------
__global__ void out_kernel(float* __restrict__ out){
    __shared__ float DS[32*33];
    __shared__ float NS[32*65];
    const int t  = threadIdx.x;
    const int it = blockIdx.x;
    const int b  = blockIdx.y;
    const int i_l = t & 31;
    const int fg  = t >> 5;
    float acc[8];
    #pragma unroll
    for (int f=0;f<8;f++) acc[f]=0.f;

    for (int jt=0; jt<8; jt++){
        #pragma unroll
        for (int i=0;i<4;i++){
            int e = t + i*256; int r = e>>5; int c = e&31;
            DS[r*33+c] = g_DA[(it*32+r)*Nn + jt*32 + c];
        }
        #pragma unroll
        for (int i=0;i<8;i++){
            int e = t + i*256; int j = e>>6; int f = e&63;
            NS[j*65+f] = g_fin[(b*Nn + jt*32 + j)*EF + f];
        }
        __syncthreads();
        #pragma unroll
        for (int j=0;j<32;j++){
            float d = DS[i_l*33 + j];
            #pragma unroll
            for (int f=0;f<8;f++) acc[f] += d * NS[j*65 + fg*8 + f];
        }
        __syncthreads();
    }
    const int i = it*32 + i_l;
    float* orow = out + (size_t)(b*Nn + i)*128;
    #pragma unroll
    for (int f=0;f<8;f++) orow[64 + fg*8 + f] = acc[f];
    for (int e=t; e<32*64; e+=256){
        int r = e>>6; int f = e&63;
        out[(size_t)(b*Nn + it*32 + r)*128 + f] = g_fin[(b*Nn + it*32 + r)*EF + f];
    }
}

extern "C" void kernel_launch(void* const* d_in, const int* in_sizes, int n_in,
                              void* d_out, int out_size){
    const float* node_fea = (const float*)d_in[0];
    const float* edge_fea = (const float*)d_in[1];
    const int*   eidx     = (const int*)  d_in[2];
    const float* dis      = (const float*)d_in[3];
    const float* Wn  = (const float*)d_in[4];
    const float* bn  = (const float*)d_in[5];
    const float* We  = (const float*)d_in[6];
    const float* be  = (const float*)d_in[7];
    const float* W1  = (const float*)d_in[8];
    const float* b1  = (const float*)d_in[9];
    const float* a1  = (const float*)d_in[10];
    const float* W2  = (const float*)d_in[11];
    const float* b2  = (const float*)d_in[12];
    const float* a2  = (const float*)d_in[13];
    const float* W3  = (const float*)d_in[14];
    const float* b3  = (const float*)d_in[15];
    const float* a3  = (const float*)d_in[16];
    const float* Wf  = (const float*)d_in[17];
    const float* bf  = (const float*)d_in[18];
    const float* DAw = (const float*)d_in[19];
    const float* DAb = (const float*)d_in[20];
    float* out = (float*)d_out;

    float *nfA, *nfB, *bceP, *finP, *efpP;
    ull *WceTP;
    cudaGetSymbolAddress((void**)&nfA,   g_nfA);
    cudaGetSymbolAddress((void**)&nfB,   g_nfB);
    cudaGetSymbolAddress((void**)&bceP,  g_bce);
    cudaGetSymbolAddress((void**)&WceTP, g_WceT);
    cudaGetSymbolAddress((void**)&finP,  g_fin);
    cudaGetSymbolAddress((void**)&efpP,  g_efp);

    cudaFuncSetAttribute(conv_kernel,
                         cudaFuncAttributeMaxDynamicSharedMemorySize, CONV_SMEM);

    const float* Ws[3] = {W1,W2,W3};
    const float* bs[3] = {b1,b2,b3};
    const float* as[3] = {a1,a2,a3};

    // launches: pre(1), wce2(2), sg1(3), conv1(4 = profiled)
    pre_kernel<<<PADB + ROWS/8, 256>>>(edge_fea, node_fea, Wn, bn, nfA);
    wce2_kernel<<<dim3(128,3), 48>>>(W1, W2, W3, We, be);

    float* nin  = nfA;
    float* nout = nfB;
    for (int l=0; l<3; l++){
        sg_kernel<<<dim3(ROWS/128, 4), 256>>>(nin, Ws[l], bs[l], bceP + l*256);
        conv_kernel<<<NGRP*2, 256, CONV_SMEM>>>(nin, nout, efpP, eidx,
                                                WceTP + (size_t)l*OEF*128, as[l]);
        float* tmp = nin; nin = nout; nout = tmp;
    }

    da_kernel<<<256, 256>>>(dis, DAw, DAb);
    linear_kernel<NF,EF,16><<<ROWS/16, EF>>>(nin, Wf, bf, finP);
    out_kernel<<<dim3(8, Bn), 256>>>(out);
}

// round 14
// speedup vs baseline: 1.3166x; 1.3158x over previous
#include <cuda_runtime.h>
#include <math.h>

// R14 = R13's conv/pre/wce2 (conv measured 151.7us) + R10's sg (measured ~90us/layer).
// R13's sg B-dup staging doubled sg inner-loop LDS traffic -> reverted.

#define Bn   64
#define Nn   256
#define Mm   16
#define ONF  92
#define OEF  41
#define NF   128
#define EF   64
#define ROWS (Bn*Nn)   // 16384
#define NGRP (ROWS/8)  // 2048

typedef unsigned long long ull;

// ---- scratch ----
__device__ float g_nfA[ROWS*NF];
__device__ float g_nfB[ROWS*NF];
// interleaved pairs per node (512 floats):
//  [2o+0]=S_F(o) [2o+1]=S_C(o) ; [256+2o+0]=G_F(o) [256+2o+1]=G_C(o)
__device__ float g_SG[ROWS*512];
__device__ float g_efp[NGRP*OEF*128];  // GEMM-ready: [group][k][row], exact 41 k
__device__ ull   g_WceT[3*OEF*128];    // [l][k][o] = pack(WceF[o][k], WceC[o][k])
__device__ float g_bce[3*256];
__device__ float g_DA[Nn*Nn];
__device__ float g_fin[ROWS*EF];

__device__ __forceinline__ float tanh_ap(float x){
    float r; asm("tanh.approx.f32 %0, %1;" : "=f"(r) : "f"(x)); return r;
}
__device__ __forceinline__ float sigm(float x){
    return fmaf(tanh_ap(0.5f*x), 0.5f, 0.5f);
}
__device__ __forceinline__ float sigm_exact(float x){
    return __fdividef(1.f, 1.f + __expf(-x));
}
__device__ __forceinline__ float softplusf(float x){
    return fmaxf(x, 0.f) + __logf(1.f + __expf(-fabsf(x)));
}

__device__ __forceinline__ ull pack2(float lo, float hi){
    ull r; asm("mov.b64 %0, {%1, %2};" : "=l"(r) : "f"(lo), "f"(hi)); return r;
}
__device__ __forceinline__ void unpack2(ull v, float &lo, float &hi){
    asm("mov.b64 {%0, %1}, %2;" : "=f"(lo), "=f"(hi) : "l"(v));
}
__device__ __forceinline__ void fma2(ull &d, ull a, ull b){
    asm("fma.rn.f32x2 %0, %1, %2, %0;" : "+l"(d) : "l"(a), "l"(b));
}
__device__ __forceinline__ ull add2(ull a, ull b){
    ull r; asm("add.rn.f32x2 %0, %1, %2;" : "=l"(r) : "l"(a), "l"(b)); return r;
}

// ======== fused pre: ef transpose (exact 41k) + embed linear ========
#define PADB ((NGRP*OEF*128)/256)    // 41984
__global__ void pre_kernel(const float* __restrict__ ef,
                           const float* __restrict__ X, const float* __restrict__ W,
                           const float* __restrict__ bias, float* __restrict__ Y){
    __shared__ float Wsh[ONF*(NF+1)];
    __shared__ __align__(16) float Xsh[ONF*8];
    const int t = threadIdx.x;
    if (blockIdx.x < PADB){
        int i = blockIdx.x*256 + t;
        int group = i / (OEF*128);
        int rem   = i - group*(OEF*128);
        int k = rem >> 7, r = rem & 127;   // r = (node&7)*16 + m
        g_efp[i] = ef[((size_t)group*128 + r)*OEF + k];
        return;
    }
    const int rb = (blockIdx.x - PADB) * 8;
    for (int e = t; e < ONF*NF; e += 256){
        int o = e / ONF, k = e - o*ONF;
        Wsh[k*(NF+1) + o] = W[e];
    }
    for (int e = t; e < 8*ONF; e += 256){
        int r = e / ONF, k = e - r*ONF;
        Xsh[k*8 + r] = X[(size_t)(rb+r)*ONF + k];
    }
    __syncthreads();
    if (t < NF){
        float acc[8];
        #pragma unroll
        for (int r=0;r<8;r++) acc[r]=0.f;
        #pragma unroll 2
        for (int k=0;k<ONF;k++){
            float w = Wsh[k*(NF+1)+t];
            const float4* xr = (const float4*)(Xsh + k*8);
            float4 x0 = xr[0], x1 = xr[1];
            acc[0]+=x0.x*w; acc[1]+=x0.y*w; acc[2]+=x0.z*w; acc[3]+=x0.w*w;
            acc[4]+=x1.x*w; acc[5]+=x1.y*w; acc[6]+=x1.z*w; acc[7]+=x1.w*w;
        }
        float bv = bias[t];
        #pragma unroll
        for (int r=0;r<8;r++) Y[(size_t)(rb+r)*NF + t] = acc[r] + bv;
    }
}

// ======== wce2: g_WceT[l][k][o] (41 k rows) ; bce ========
__global__ void wce2_kernel(const float* __restrict__ W1,const float* __restrict__ W2,
                            const float* __restrict__ W3,const float* __restrict__ We,
                            const float* __restrict__ be){
    const int o = blockIdx.x;       // 0..127
    const int l = blockIdx.y;       // 0..2
    const int t = threadIdx.x;      // 0..47
    const float* W = (l==0)?W1:((l==1)?W2:W3);
    const float* rF = W + (size_t)o*320 + 256;
    const float* rC = W + (size_t)(o+128)*320 + 256;
    if (t < OEF){
        float aF = 0.f, aC = 0.f;
        for (int e=0;e<EF;e++){
            float v = We[e*OEF + t];
            aF += rF[e]*v; aC += rC[e]*v;
        }
        g_WceT[(l*OEF + t)*128 + o] = pack2(aF, aC);
    } else if (t == 44){
        float a = 0.f;
        for (int e=0;e<EF;e++) a += rF[e]*be[e];
        g_bce[l*256 + o] = a;
    } else if (t == 45){
        float a = 0.f;
        for (int e=0;e<EF;e++) a += rC[e]*be[e];
        g_bce[l*256 + o + 128] = a;
    }
}

__global__ void da_kernel(const float* __restrict__ dis,
                          const float* __restrict__ wp, const float* __restrict__ bp){
    int i = blockIdx.x*256 + threadIdx.x;
    g_DA[i] = sigm_exact(wp[0]*dis[i] + bp[0]);
}

// ======== SG GEMM (R10 version: float4 B reads, pack2 in inner loop) ========
__global__ __launch_bounds__(256,2)
void sg_kernel(const float* __restrict__ nf, const float* __restrict__ W,
               const float* __restrict__ bl, const float* __restrict__ bce){
    __shared__ float Ash[2][16][128];
    __shared__ float Bsh[2][16][128];
    const int t  = threadIdx.x;
    const int rb = blockIdx.x * 128;
    const int cb = blockIdx.y * 128;
    const int tx = t & 15;
    const int ty = t >> 4;

    const int sr = t >> 1;
    const int sq = (t & 1) * 8;
    const float* Arow = nf + (size_t)(rb + sr)*NF + sq;
    const int ogc = cb + sr;
    const float* Brow = (ogc < 256) ? (W + ogc*320 + sq)
                                    : (W + (ogc-256)*320 + 128 + sq);

    float4 pa0 = *(const float4*)(Arow + 0);
    float4 pa1 = *(const float4*)(Arow + 4);
    float4 pb0 = *(const float4*)(Brow + 0);
    float4 pb1 = *(const float4*)(Brow + 4);

    ull acc[4][8];
    #pragma unroll
    for (int p=0;p<4;p++)
        #pragma unroll
        for (int j=0;j<8;j++) acc[p][j] = 0ULL;

    #pragma unroll 1
    for (int kt=0; kt<128; kt+=16){
        const int buf = (kt >> 4) & 1;
        Ash[buf][sq+0][sr]=pa0.x; Ash[buf][sq+1][sr]=pa0.y;
        Ash[buf][sq+2][sr]=pa0.z; Ash[buf][sq+3][sr]=pa0.w;
        Ash[buf][sq+4][sr]=pa1.x; Ash[buf][sq+5][sr]=pa1.y;
        Ash[buf][sq+6][sr]=pa1.z; Ash[buf][sq+7][sr]=pa1.w;
        Bsh[buf][sq+0][sr]=pb0.x; Bsh[buf][sq+1][sr]=pb0.y;
        Bsh[buf][sq+2][sr]=pb0.z; Bsh[buf][sq+3][sr]=pb0.w;
        Bsh[buf][sq+4][sr]=pb1.x; Bsh[buf][sq+5][sr]=pb1.y;
        Bsh[buf][sq+6][sr]=pb1.z; Bsh[buf][sq+7][sr]=pb1.w;
        __syncthreads();
        if (kt + 16 < 128){
            pa0 = *(const float4*)(Arow + kt + 16);
            pa1 = *(const float4*)(Arow + kt + 20);
            pb0 = *(const float4*)(Brow + kt + 16);
            pb1 = *(const float4*)(Brow + kt + 20);
        }
        #pragma unroll 8
        for (int k=0;k<16;k++){
            ulonglong2 a01 = *(const ulonglong2*)&Ash[buf][k][ty*8];
            ulonglong2 a23 = *(const ulonglong2*)&Ash[buf][k][ty*8+4];
            float4 b0 = *(const float4*)&Bsh[buf][k][tx*8];
            float4 b1 = *(const float4*)&Bsh[buf][k][tx*8+4];
            ull bb0=pack2(b0.x,b0.x), bb1=pack2(b0.y,b0.y);
            ull bb2=pack2(b0.z,b0.z), bb3=pack2(b0.w,b0.w);
            ull bb4=pack2(b1.x,b1.x), bb5=pack2(b1.y,b1.y);
            ull bb6=pack2(b1.z,b1.z), bb7=pack2(b1.w,b1.w);
            fma2(acc[0][0],a01.x,bb0); fma2(acc[0][1],a01.x,bb1);
            fma2(acc[0][2],a01.x,bb2); fma2(acc[0][3],a01.x,bb3);
            fma2(acc[0][4],a01.x,bb4); fma2(acc[0][5],a01.x,bb5);
            fma2(acc[0][6],a01.x,bb6); fma2(acc[0][7],a01.x,bb7);
            fma2(acc[1][0],a01.y,bb0); fma2(acc[1][1],a01.y,bb1);
            fma2(acc[1][2],a01.y,bb2); fma2(acc[1][3],a01.y,bb3);
            fma2(acc[1][4],a01.y,bb4); fma2(acc[1][5],a01.y,bb5);
            fma2(acc[1][6],a01.y,bb6); fma2(acc[1][7],a01.y,bb7);
            fma2(acc[2][0],a23.x,bb0); fma2(acc[2][1],a23.x,bb1);
            fma2(acc[2][2],a23.x,bb2); fma2(acc[2][3],a23.x,bb3);
            fma2(acc[2][4],a23.x,bb4); fma2(acc[2][5],a23.x,bb5);
            fma2(acc[2][6],a23.x,bb6); fma2(acc[2][7],a23.x,bb7);
            fma2(acc[3][0],a23.y,bb0); fma2(acc[3][1],a23.y,bb1);
            fma2(acc[3][2],a23.y,bb2); fma2(acc[3][3],a23.y,bb3);
            fma2(acc[3][4],a23.y,bb4); fma2(acc[3][5],a23.y,bb5);
            fma2(acc[3][6],a23.y,bb6); fma2(acc[3][7],a23.y,bb7);
        }
        __syncthreads();
    }
    #pragma unroll
    for (int j=0;j<8;j++){
        const int c = cb + tx*8 + j;
        const int aoff = (c & 256) + 2*(c & 127) + ((c >> 7) & 1);
        const float bias = (c < 256) ? (bl[c] + bce[c]) : 0.f;
        #pragma unroll
        for (int p=0;p<4;p++){
            float lo, hi; unpack2(acc[p][j], lo, hi);
            const int row = rb + ty*8 + 2*p;
            g_SG[(size_t)row*512 + aoff]     = lo + bias;
            g_SG[(size_t)(row+1)*512 + aoff] = hi + bias;
        }
    }
}

// ======== conv: 41-k edge-GEMM, coalesced dup staging (R13, measured 151.7us) ========
#define CONV_SMEM ((OEF*128 + OEF*64 + 8*64)*8 + 128*4)
__global__ __launch_bounds__(256,2)
void conv_kernel(const float* __restrict__ nf_in, float* __restrict__ nf_out,
                 const float* __restrict__ efpT, const int* __restrict__ eidx,
                 const ull* __restrict__ WceT, const float* __restrict__ alphap){
    extern __shared__ __align__(16) char smembuf[];
    ull*  A_sh   = (ull*)smembuf;           // [41][128] dup pairs
    ull*  B_sh   = A_sh + OEF*128;          // [41][64]
    ull*  sPp_sh = B_sh + OEF*64;           // [8][64]
    int*  idx_sh = (int*)(sPp_sh + 8*64);   // [128]
    const int t  = threadIdx.x;
    const int tx = t & 15;
    const int ty = t >> 4;
    const int group = blockIdx.x >> 1;
    const int H = blockIdx.x & 1;
    const int node0 = group * 8;

    // stage A dup: float2 source unit -> one STS.128 at consecutive 16B
    {
        const float2* src = (const float2*)(efpT + (size_t)group*(OEF*128));
        ulonglong2* dst = (ulonglong2*)A_sh;
        #pragma unroll
        for (int p=0;p<11;p++){
            int e = t + p*256;               // 2624 float2 units
            if (e < (OEF*128)/2){
                float2 v = src[e];
                ulonglong2 d;
                d.x = pack2(v.x, v.x);
                d.y = pack2(v.y, v.y);
                dst[e] = d;
            }
        }
    }
    // stage B: 41 k x 64 o-pairs
    {
        #pragma unroll
        for (int p=0;p<11;p++){
            int e = t + p*256;               // 2624
            if (e < OEF*64){
                int k = e >> 6, op = e & 63;
                B_sh[e] = WceT[k*128 + H*64 + op];
            }
        }
    }
    // stage S-pairs
    {
        #pragma unroll
        for (int p=0;p<2;p++){
            int e = t + p*256;
            int nl = e >> 6, op = e & 63;
            sPp_sh[e] = *(const ull*)(g_SG + (size_t)(node0+nl)*512 + 2*(H*64+op));
        }
    }
    if (t < 128) idx_sh[t] = eidx[node0*Mm + t];
    __syncthreads();

    ull acc[8][4];
    #pragma unroll
    for (int i=0;i<8;i++)
        #pragma unroll
        for (int q=0;q<4;q++) acc[i][q] = 0ULL;

    #pragma unroll 4
    for (int k=0;k<OEF;k++){
        const ull* Ak = A_sh + k*128 + ty*8;
        const ull* Bk = B_sh + k*64 + tx*4;
        ulonglong2 a01 = *(const ulonglong2*)Ak;
        ulonglong2 a23 = *(const ulonglong2*)(Ak+2);
        ulonglong2 a45 = *(const ulonglong2*)(Ak+4);
        ulonglong2 a67 = *(const ulonglong2*)(Ak+6);
        ulonglong2 b01 = *(const ulonglong2*)Bk;
        ulonglong2 b23 = *(const ulonglong2*)(Bk+2);
        fma2(acc[0][0],a01.x,b01.x); fma2(acc[0][1],a01.x,b01.y);
        fma2(acc[0][2],a01.x,b23.x); fma2(acc[0][3],a01.x,b23.y);
        fma2(acc[1][0],a01.y,b01.x); fma2(acc[1][1],a01.y,b01.y);
        fma2(acc[1][2],a01.y,b23.x); fma2(acc[1][3],a01.y,b23.y);
        fma2(acc[2][0],a23.x,b01.x); fma2(acc[2][1],a23.x,b01.y);
        fma2(acc[2][2],a23.x,b23.x); fma2(acc[2][3],a23.x,b23.y);
        fma2(acc[3][0],a23.y,b01.x); fma2(acc[3][1],a23.y,b01.y);
        fma2(acc[3][2],a23.y,b23.x); fma2(acc[3][3],a23.y,b23.y);
        fma2(acc[4][0],a45.x,b01.x); fma2(acc[4][1],a45.x,b01.y);
        fma2(acc[4][2],a45.x,b23.x); fma2(acc[4][3],a45.x,b23.y);
        fma2(acc[5][0],a45.y,b01.x); fma2(acc[5][1],a45.y,b01.y);
        fma2(acc[5][2],a45.y,b23.x); fma2(acc[5][3],a45.y,b23.y);
        fma2(acc[6][0],a67.x,b01.x); fma2(acc[6][1],a67.x,b01.y);
        fma2(acc[6][2],a67.x,b23.x); fma2(acc[6][3],a67.x,b23.y);
        fma2(acc[7][0],a67.y,b01.x); fma2(acc[7][1],a67.y,b01.y);
        fma2(acc[7][2],a67.y,b23.x); fma2(acc[7][3],a67.y,b23.y);
    }

    // epilogue
    const int nl   = ty >> 1;
    const int node = node0 + nl;
    const int m0   = (ty & 1) * 8;
    const int bb   = node >> 8;
    const float* SGb = g_SG + (size_t)bb*Nn*512 + 256 + 2*(H*64);
    const ull sp0 = sPp_sh[nl*64 + tx*4 + 0];
    const ull sp1 = sPp_sh[nl*64 + tx*4 + 1];
    const ull sp2 = sPp_sh[nl*64 + tx*4 + 2];
    const ull sp3 = sPp_sh[nl*64 + tx*4 + 3];
    float part0=0.f, part1=0.f, part2=0.f, part3=0.f;
    #pragma unroll
    for (int i=0;i<8;i++){
        const int j  = idx_sh[nl*Mm + m0 + i];
        const int jc = (j < 0) ? 0 : j;
        const ull* Gp = (const ull*)(SGb + (size_t)jc*512) + tx*4;
        ulonglong2 g01 = *(const ulonglong2*)Gp;
        ulonglong2 g23 = *((const ulonglong2*)Gp + 1);
        ull v0 = add2(add2(acc[i][0], sp0), g01.x);
        ull v1 = add2(add2(acc[i][1], sp1), g01.y);
        ull v2 = add2(add2(acc[i][2], sp2), g23.x);
        ull v3 = add2(add2(acc[i][3], sp3), g23.y);
        float f,c;
        const float msk = (j >= 0) ? 1.f : 0.f;
        unpack2(v0,f,c); part0 += msk*sigm(f)*softplusf(c);
        unpack2(v1,f,c); part1 += msk*sigm(f)*softplusf(c);
        unpack2(v2,f,c); part2 += msk*sigm(f)*softplusf(c);
        unpack2(v3,f,c); part3 += msk*sigm(f)*softplusf(c);
    }
    const float tt0 = part0 + __shfl_xor_sync(0xFFFFFFFFu, part0, 16);
    const float tt1 = part1 + __shfl_xor_sync(0xFFFFFFFFu, part1, 16);
    const float tt2 = part2 + __shfl_xor_sync(0xFFFFFFFFu, part2, 16);
    const float tt3 = part3 + __shfl_xor_sync(0xFFFFFFFFu, part3, 16);
    if ((ty & 1) == 0){
        const float alpha = alphap[0];
        const size_t off = (size_t)node*NF + H*64 + tx*4;
        const float4 sv = *(const float4*)(nf_in + off);
        float4 o4;
        o4.x = softplusf(fmaf(alpha, sv.x, tt0));
        o4.y = softplusf(fmaf(alpha, sv.y, tt1));
        o4.z = softplusf(fmaf(alpha, sv.z, tt2));
        o4.w = softplusf(fmaf(alpha, sv.w, tt3));
        *(float4*)(nf_out + off) = o4;
    }
}

// ---------------- final linear ----------------
template<int IN,int OUT,int RPB>
__global__ void linear_kernel(const float* __restrict__ X, const float* __restrict__ W,
                              const float* __restrict__ bias, float* __restrict__ Y){
    __shared__ float Wsh[IN*(OUT+1)];
    __shared__ __align__(16) float Xsh[IN*RPB];
    const int rb = blockIdx.x * RPB;
    const int t  = threadIdx.x;
    for (int e = t; e < IN*OUT; e += OUT){
        int o = e / IN, k = e - o*IN;
        Wsh[k*(OUT+1) + o] = W[e];
    }
    for (int e = t; e < RPB*IN; e += OUT){
        int r = e / IN, k = e - r*IN;
        Xsh[k*RPB + r] = X[(size_t)(rb+r)*IN + k];
    }
    __syncthreads();
    float acc[RPB];
    #pragma unroll
    for (int r=0;r<RPB;r++) acc[r]=0.f;
    #pragma unroll 2
    for (int k=0;k<IN;k++){
        float w = Wsh[k*(OUT+1)+t];
        const float4* xr = (const float4*)(Xsh + k*RPB);
        #pragma unroll
        for (int r4=0;r4<RPB/4;r4++){
            float4 xv = xr[r4];
            acc[4*r4+0] += xv.x*w; acc[4*r4+1] += xv.y*w;
            acc[4*r4+2] += xv.z*w; acc[4*r4+3] += xv.w*w;
        }
    }
    float bv = bias[t];
    #pragma unroll
    for (int r=0;r<RPB;r++) Y[(size_t)(rb+r)*OUT + t] = acc[r] + bv;
}

// -------- output --------
__global__ void out_kernel(float* __restrict__ out){
    __shared__ float DS[32*33];
    __shared__ float NS[32*65];
    const int t  = threadIdx.x;
    const int it = blockIdx.x;
    const int b  = blockIdx.y;
    const int i_l = t & 31;
    const int fg  = t >> 5;
    float acc[8];
    #pragma unroll
    for (int f=0;f<8;f++) acc[f]=0.f;

    for (int jt=0; jt<8; jt++){
        #pragma unroll
        for (int i=0;i<4;i++){
            int e = t + i*256; int r = e>>5; int c = e&31;
            DS[r*33+c] = g_DA[(it*32+r)*Nn + jt*32 + c];
        }
        #pragma unroll
        for (int i=0;i<8;i++){
            int e = t + i*256; int j = e>>6; int f = e&63;
            NS[j*65+f] = g_fin[(b*Nn + jt*32 + j)*EF + f];
        }
        __syncthreads();
        #pragma unroll
        for (int j=0;j<32;j++){
            float d = DS[i_l*33 + j];
            #pragma unroll
            for (int f=0;f<8;f++) acc[f] += d * NS[j*65 + fg*8 + f];
        }
        __syncthreads();
    }
    const int i = it*32 + i_l;
    float* orow = out + (size_t)(b*Nn + i)*128;
    #pragma unroll
    for (int f=0;f<8;f++) orow[64 + fg*8 + f] = acc[f];
    for (int e=t; e<32*64; e+=256){
        int r = e>>6; int f = e&63;
        out[(size_t)(b*Nn + it*32 + r)*128 + f] = g_fin[(b*Nn + it*32 + r)*EF + f];
    }
}

extern "C" void kernel_launch(void* const* d_in, const int* in_sizes, int n_in,
                              void* d_out, int out_size){
    const float* node_fea = (const float*)d_in[0];
    const float* edge_fea = (const float*)d_in[1];
    const int*   eidx     = (const int*)  d_in[2];
    const float* dis      = (const float*)d_in[3];
    const float* Wn  = (const float*)d_in[4];
    const float* bn  = (const float*)d_in[5];
    const float* We  = (const float*)d_in[6];
    const float* be  = (const float*)d_in[7];
    const float* W1  = (const float*)d_in[8];
    const float* b1  = (const float*)d_in[9];
    const float* a1  = (const float*)d_in[10];
    const float* W2  = (const float*)d_in[11];
    const float* b2  = (const float*)d_in[12];
    const float* a2  = (const float*)d_in[13];
    const float* W3  = (const float*)d_in[14];
    const float* b3  = (const float*)d_in[15];
    const float* a3  = (const float*)d_in[16];
    const float* Wf  = (const float*)d_in[17];
    const float* bf  = (const float*)d_in[18];
    const float* DAw = (const float*)d_in[19];
    const float* DAb = (const float*)d_in[20];
    float* out = (float*)d_out;

    float *nfA, *nfB, *bceP, *finP, *efpP;
    ull *WceTP;
    cudaGetSymbolAddress((void**)&nfA,   g_nfA);
    cudaGetSymbolAddress((void**)&nfB,   g_nfB);
    cudaGetSymbolAddress((void**)&bceP,  g_bce);
    cudaGetSymbolAddress((void**)&WceTP, g_WceT);
    cudaGetSymbolAddress((void**)&finP,  g_fin);
    cudaGetSymbolAddress((void**)&efpP,  g_efp);

    cudaFuncSetAttribute(conv_kernel,
                         cudaFuncAttributeMaxDynamicSharedMemorySize, CONV_SMEM);

    const float* Ws[3] = {W1,W2,W3};
    const float* bs[3] = {b1,b2,b3};
    const float* as[3] = {a1,a2,a3};

    // launches: pre(1), wce2(2), sg1(3), conv1(4 = profiled)
    pre_kernel<<<PADB + ROWS/8, 256>>>(edge_fea, node_fea, Wn, bn, nfA);
    wce2_kernel<<<dim3(128,3), 48>>>(W1, W2, W3, We, be);

    float* nin  = nfA;
    float* nout = nfB;
    for (int l=0; l<3; l++){
        sg_kernel<<<dim3(ROWS/128, 4), 256>>>(nin, Ws[l], bs[l], bceP + l*256);
        conv_kernel<<<NGRP*2, 256, CONV_SMEM>>>(nin, nout, efpP, eidx,
                                                WceTP + (size_t)l*OEF*128, as[l]);
        float* tmp = nin; nin = nout; nout = tmp;
    }

    da_kernel<<<256, 256>>>(dis, DAw, DAb);
    linear_kernel<NF,EF,16><<<ROWS/16, EF>>>(nin, Wf, bf, finP);
    out_kernel<<<dim3(8, Bn), 256>>>(out);
}

// round 15
// speedup vs baseline: 1.4120x; 1.0725x over previous
#include <cuda_runtime.h>
#include <math.h>

// R15 = R14 with conv A operand stored NON-duplicated in smem (plain float copy
// from g_efp) and duplicated in-register via pack2 (sg's proven structure).
// Cuts conv inner-loop LDS phases 24 -> 16 per warp-k (the measured 1.5x
// LDS:FMA imbalance behind the 87% L1 ceiling).

#define Bn   64
#define Nn   256
#define Mm   16
#define ONF  92
#define OEF  41
#define NF   128
#define EF   64
#define ROWS (Bn*Nn)   // 16384
#define NGRP (ROWS/8)  // 2048

typedef unsigned long long ull;

// ---- scratch ----
__device__ float g_nfA[ROWS*NF];
__device__ float g_nfB[ROWS*NF];
// interleaved pairs per node (512 floats):
//  [2o+0]=S_F(o) [2o+1]=S_C(o) ; [256+2o+0]=G_F(o) [256+2o+1]=G_C(o)
__device__ float g_SG[ROWS*512];
__device__ float g_efp[NGRP*OEF*128];  // GEMM-ready: [group][k][row], exact 41 k
__device__ ull   g_WceT[3*OEF*128];    // [l][k][o] = pack(WceF[o][k], WceC[o][k])
__device__ float g_bce[3*256];
__device__ float g_DA[Nn*Nn];
__device__ float g_fin[ROWS*EF];

__device__ __forceinline__ float tanh_ap(float x){
    float r; asm("tanh.approx.f32 %0, %1;" : "=f"(r) : "f"(x)); return r;
}
__device__ __forceinline__ float sigm(float x){
    return fmaf(tanh_ap(0.5f*x), 0.5f, 0.5f);
}
__device__ __forceinline__ float sigm_exact(float x){
    return __fdividef(1.f, 1.f + __expf(-x));
}
__device__ __forceinline__ float softplusf(float x){
    return fmaxf(x, 0.f) + __logf(1.f + __expf(-fabsf(x)));
}

__device__ __forceinline__ ull pack2(float lo, float hi){
    ull r; asm("mov.b64 %0, {%1, %2};" : "=l"(r) : "f"(lo), "f"(hi)); return r;
}
__device__ __forceinline__ void unpack2(ull v, float &lo, float &hi){
    asm("mov.b64 {%0, %1}, %2;" : "=f"(lo), "=f"(hi) : "l"(v));
}
__device__ __forceinline__ void fma2(ull &d, ull a, ull b){
    asm("fma.rn.f32x2 %0, %1, %2, %0;" : "+l"(d) : "l"(a), "l"(b));
}
__device__ __forceinline__ ull add2(ull a, ull b){
    ull r; asm("add.rn.f32x2 %0, %1, %2;" : "=l"(r) : "l"(a), "l"(b)); return r;
}

// ======== fused pre: ef transpose (exact 41k) + embed linear ========
#define PADB ((NGRP*OEF*128)/256)    // 41984
__global__ void pre_kernel(const float* __restrict__ ef,
                           const float* __restrict__ X, const float* __restrict__ W,
                           const float* __restrict__ bias, float* __restrict__ Y){
    __shared__ float Wsh[ONF*(NF+1)];
    __shared__ __align__(16) float Xsh[ONF*8];
    const int t = threadIdx.x;
    if (blockIdx.x < PADB){
        int i = blockIdx.x*256 + t;
        int group = i / (OEF*128);
        int rem   = i - group*(OEF*128);
        int k = rem >> 7, r = rem & 127;   // r = (node&7)*16 + m
        g_efp[i] = ef[((size_t)group*128 + r)*OEF + k];
        return;
    }
    const int rb = (blockIdx.x - PADB) * 8;
    for (int e = t; e < ONF*NF; e += 256){
        int o = e / ONF, k = e - o*ONF;
        Wsh[k*(NF+1) + o] = W[e];
    }
    for (int e = t; e < 8*ONF; e += 256){
        int r = e / ONF, k = e - r*ONF;
        Xsh[k*8 + r] = X[(size_t)(rb+r)*ONF + k];
    }
    __syncthreads();
    if (t < NF){
        float acc[8];
        #pragma unroll
        for (int r=0;r<8;r++) acc[r]=0.f;
        #pragma unroll 2
        for (int k=0;k<ONF;k++){
            float w = Wsh[k*(NF+1)+t];
            const float4* xr = (const float4*)(Xsh + k*8);
            float4 x0 = xr[0], x1 = xr[1];
            acc[0]+=x0.x*w; acc[1]+=x0.y*w; acc[2]+=x0.z*w; acc[3]+=x0.w*w;
            acc[4]+=x1.x*w; acc[5]+=x1.y*w; acc[6]+=x1.z*w; acc[7]+=x1.w*w;
        }
        float bv = bias[t];
        #pragma unroll
        for (int r=0;r<8;r++) Y[(size_t)(rb+r)*NF + t] = acc[r] + bv;
    }
}

// ======== wce2: g_WceT[l][k][o] (41 k rows) ; bce ========
__global__ void wce2_kernel(const float* __restrict__ W1,const float* __restrict__ W2,
                            const float* __restrict__ W3,const float* __restrict__ We,
                            const float* __restrict__ be){
    const int o = blockIdx.x;       // 0..127
    const int l = blockIdx.y;       // 0..2
    const int t = threadIdx.x;      // 0..47
    const float* W = (l==0)?W1:((l==1)?W2:W3);
    const float* rF = W + (size_t)o*320 + 256;
    const float* rC = W + (size_t)(o+128)*320 + 256;
    if (t < OEF){
        float aF = 0.f, aC = 0.f;
        for (int e=0;e<EF;e++){
            float v = We[e*OEF + t];
            aF += rF[e]*v; aC += rC[e]*v;
        }
        g_WceT[(l*OEF + t)*128 + o] = pack2(aF, aC);
    } else if (t == 44){
        float a = 0.f;
        for (int e=0;e<EF;e++) a += rF[e]*be[e];
        g_bce[l*256 + o] = a;
    } else if (t == 45){
        float a = 0.f;
        for (int e=0;e<EF;e++) a += rC[e]*be[e];
        g_bce[l*256 + o + 128] = a;
    }
}

__global__ void da_kernel(const float* __restrict__ dis,
                          const float* __restrict__ wp, const float* __restrict__ bp){
    int i = blockIdx.x*256 + threadIdx.x;
    g_DA[i] = sigm_exact(wp[0]*dis[i] + bp[0]);
}

// ======== SG GEMM (R10 version, unchanged) ========
__global__ __launch_bounds__(256,2)
void sg_kernel(const float* __restrict__ nf, const float* __restrict__ W,
               const float* __restrict__ bl, const float* __restrict__ bce){
    __shared__ float Ash[2][16][128];
    __shared__ float Bsh[2][16][128];
    const int t  = threadIdx.x;
    const int rb = blockIdx.x * 128;
    const int cb = blockIdx.y * 128;
    const int tx = t & 15;
    const int ty = t >> 4;

    const int sr = t >> 1;
    const int sq = (t & 1) * 8;
    const float* Arow = nf + (size_t)(rb + sr)*NF + sq;
    const int ogc = cb + sr;
    const float* Brow = (ogc < 256) ? (W + ogc*320 + sq)
                                    : (W + (ogc-256)*320 + 128 + sq);

    float4 pa0 = *(const float4*)(Arow + 0);
    float4 pa1 = *(const float4*)(Arow + 4);
    float4 pb0 = *(const float4*)(Brow + 0);
    float4 pb1 = *(const float4*)(Brow + 4);

    ull acc[4][8];
    #pragma unroll
    for (int p=0;p<4;p++)
        #pragma unroll
        for (int j=0;j<8;j++) acc[p][j] = 0ULL;

    #pragma unroll 1
    for (int kt=0; kt<128; kt+=16){
        const int buf = (kt >> 4) & 1;
        Ash[buf][sq+0][sr]=pa0.x; Ash[buf][sq+1][sr]=pa0.y;
        Ash[buf][sq+2][sr]=pa0.z; Ash[buf][sq+3][sr]=pa0.w;
        Ash[buf][sq+4][sr]=pa1.x; Ash[buf][sq+5][sr]=pa1.y;
        Ash[buf][sq+6][sr]=pa1.z; Ash[buf][sq+7][sr]=pa1.w;
        Bsh[buf][sq+0][sr]=pb0.x; Bsh[buf][sq+1][sr]=pb0.y;
        Bsh[buf][sq+2][sr]=pb0.z; Bsh[buf][sq+3][sr]=pb0.w;
        Bsh[buf][sq+4][sr]=pb1.x; Bsh[buf][sq+5][sr]=pb1.y;
        Bsh[buf][sq+6][sr]=pb1.z; Bsh[buf][sq+7][sr]=pb1.w;
        __syncthreads();
        if (kt + 16 < 128){
            pa0 = *(const float4*)(Arow + kt + 16);
            pa1 = *(const float4*)(Arow + kt + 20);
            pb0 = *(const float4*)(Brow + kt + 16);
            pb1 = *(const float4*)(Brow + kt + 20);
        }
        #pragma unroll 8
        for (int k=0;k<16;k++){
            ulonglong2 a01 = *(const ulonglong2*)&Ash[buf][k][ty*8];
            ulonglong2 a23 = *(const ulonglong2*)&Ash[buf][k][ty*8+4];
            float4 b0 = *(const float4*)&Bsh[buf][k][tx*8];
            float4 b1 = *(const float4*)&Bsh[buf][k][tx*8+4];
            ull bb0=pack2(b0.x,b0.x), bb1=pack2(b0.y,b0.y);
            ull bb2=pack2(b0.z,b0.z), bb3=pack2(b0.w,b0.w);
            ull bb4=pack2(b1.x,b1.x), bb5=pack2(b1.y,b1.y);
            ull bb6=pack2(b1.z,b1.z), bb7=pack2(b1.w,b1.w);
            fma2(acc[0][0],a01.x,bb0); fma2(acc[0][1],a01.x,bb1);
            fma2(acc[0][2],a01.x,bb2); fma2(acc[0][3],a01.x,bb3);
            fma2(acc[0][4],a01.x,bb4); fma2(acc[0][5],a01.x,bb5);
            fma2(acc[0][6],a01.x,bb6); fma2(acc[0][7],a01.x,bb7);
            fma2(acc[1][0],a01.y,bb0); fma2(acc[1][1],a01.y,bb1);
            fma2(acc[1][2],a01.y,bb2); fma2(acc[1][3],a01.y,bb3);
            fma2(acc[1][4],a01.y,bb4); fma2(acc[1][5],a01.y,bb5);
            fma2(acc[1][6],a01.y,bb6); fma2(acc[1][7],a01.y,bb7);
            fma2(acc[2][0],a23.x,bb0); fma2(acc[2][1],a23.x,bb1);
            fma2(acc[2][2],a23.x,bb2); fma2(acc[2][3],a23.x,bb3);
            fma2(acc[2][4],a23.x,bb4); fma2(acc[2][5],a23.x,bb5);
            fma2(acc[2][6],a23.x,bb6); fma2(acc[2][7],a23.x,bb7);
            fma2(acc[3][0],a23.y,bb0); fma2(acc[3][1],a23.y,bb1);
            fma2(acc[3][2],a23.y,bb2); fma2(acc[3][3],a23.y,bb3);
            fma2(acc[3][4],a23.y,bb4); fma2(acc[3][5],a23.y,bb5);
            fma2(acc[3][6],a23.y,bb6); fma2(acc[3][7],a23.y,bb7);
        }
        __syncthreads();
    }
    #pragma unroll
    for (int j=0;j<8;j++){
        const int c = cb + tx*8 + j;
        const int aoff = (c & 256) + 2*(c & 127) + ((c >> 7) & 1);
        const float bias = (c < 256) ? (bl[c] + bce[c]) : 0.f;
        #pragma unroll
        for (int p=0;p<4;p++){
            float lo, hi; unpack2(acc[p][j], lo, hi);
            const int row = rb + ty*8 + 2*p;
            g_SG[(size_t)row*512 + aoff]     = lo + bias;
            g_SG[(size_t)(row+1)*512 + aoff] = hi + bias;
        }
    }
}

// ======== conv v15: A non-dup in smem, in-register pair duplication ========
// smem: A floats [41][128] (21KB) + B ull [41][64] (21KB) + sPp (4KB) + idx
#define CONV_SMEM (OEF*128*4 + OEF*64*8 + 8*64*8 + 128*4)
__global__ __launch_bounds__(256,2)
void conv_kernel(const float* __restrict__ nf_in, float* __restrict__ nf_out,
                 const float* __restrict__ efpT, const int* __restrict__ eidx,
                 const ull* __restrict__ WceT, const float* __restrict__ alphap){
    extern __shared__ __align__(16) char smembuf[];
    float* A_sh  = (float*)smembuf;          // [41][128] plain floats
    ull*  B_sh   = (ull*)(A_sh + OEF*128);   // [41][64]
    ull*  sPp_sh = B_sh + OEF*64;            // [8][64]
    int*  idx_sh = (int*)(sPp_sh + 8*64);    // [128]
    const int t  = threadIdx.x;
    const int tx = t & 15;
    const int ty = t >> 4;
    const int group = blockIdx.x >> 1;
    const int H = blockIdx.x & 1;
    const int node0 = group * 8;

    // stage A: flat uint4 copy (1312 uint4)
    {
        const uint4* src = (const uint4*)(efpT + (size_t)group*(OEF*128));
        uint4* dst = (uint4*)A_sh;
        #pragma unroll
        for (int p=0;p<6;p++){
            int e = t + p*256;
            if (e < (OEF*128)/4) dst[e] = src[e];
        }
    }
    // stage B: 41 k x 64 o-pairs
    {
        #pragma unroll
        for (int p=0;p<11;p++){
            int e = t + p*256;               // 2624
            if (e < OEF*64){
                int k = e >> 6, op = e & 63;
                B_sh[e] = WceT[k*128 + H*64 + op];
            }
        }
    }
    // stage S-pairs
    {
        #pragma unroll
        for (int p=0;p<2;p++){
            int e = t + p*256;
            int nl = e >> 6, op = e & 63;
            sPp_sh[e] = *(const ull*)(g_SG + (size_t)(node0+nl)*512 + 2*(H*64+op));
        }
    }
    if (t < 128) idx_sh[t] = eidx[node0*Mm + t];
    __syncthreads();

    ull acc[8][4];
    #pragma unroll
    for (int i=0;i<8;i++)
        #pragma unroll
        for (int q=0;q<4;q++) acc[i][q] = 0ULL;

    #pragma unroll 4
    for (int k=0;k<OEF;k++){
        const float* Ak = A_sh + k*128 + ty*8;
        const ull*   Bk = B_sh + k*64 + tx*4;
        float4 af0 = *(const float4*)Ak;
        float4 af1 = *(const float4*)(Ak+4);
        ulonglong2 b01 = *(const ulonglong2*)Bk;
        ulonglong2 b23 = *(const ulonglong2*)(Bk+2);
        ull a0 = pack2(af0.x, af0.x);
        ull a1 = pack2(af0.y, af0.y);
        ull a2 = pack2(af0.z, af0.z);
        ull a3 = pack2(af0.w, af0.w);
        ull a4 = pack2(af1.x, af1.x);
        ull a5 = pack2(af1.y, af1.y);
        ull a6 = pack2(af1.z, af1.z);
        ull a7 = pack2(af1.w, af1.w);
        fma2(acc[0][0],a0,b01.x); fma2(acc[0][1],a0,b01.y);
        fma2(acc[0][2],a0,b23.x); fma2(acc[0][3],a0,b23.y);
        fma2(acc[1][0],a1,b01.x); fma2(acc[1][1],a1,b01.y);
        fma2(acc[1][2],a1,b23.x); fma2(acc[1][3],a1,b23.y);
        fma2(acc[2][0],a2,b01.x); fma2(acc[2][1],a2,b01.y);
        fma2(acc[2][2],a2,b23.x); fma2(acc[2][3],a2,b23.y);
        fma2(acc[3][0],a3,b01.x); fma2(acc[3][1],a3,b01.y);
        fma2(acc[3][2],a3,b23.x); fma2(acc[3][3],a3,b23.y);
        fma2(acc[4][0],a4,b01.x); fma2(acc[4][1],a4,b01.y);
        fma2(acc[4][2],a4,b23.x); fma2(acc[4][3],a4,b23.y);
        fma2(acc[5][0],a5,b01.x); fma2(acc[5][1],a5,b01.y);
        fma2(acc[5][2],a5,b23.x); fma2(acc[5][3],a5,b23.y);
        fma2(acc[6][0],a6,b01.x); fma2(acc[6][1],a6,b01.y);
        fma2(acc[6][2],a6,b23.x); fma2(acc[6][3],a6,b23.y);
        fma2(acc[7][0],a7,b01.x); fma2(acc[7][1],a7,b01.y);
        fma2(acc[7][2],a7,b23.x); fma2(acc[7][3],a7,b23.y);
    }

    // epilogue
    const int nl   = ty >> 1;
    const int node = node0 + nl;
    const int m0   = (ty & 1) * 8;
    const int bb   = node >> 8;
    const float* SGb = g_SG + (size_t)bb*Nn*512 + 256 + 2*(H*64);
    const ull sp0 = sPp_sh[nl*64 + tx*4 + 0];
    const ull sp1 = sPp_sh[nl*64 + tx*4 + 1];
    const ull sp2 = sPp_sh[nl*64 + tx*4 + 2];
    const ull sp3 = sPp_sh[nl*64 + tx*4 + 3];
    float part0=0.f, part1=0.f, part2=0.f, part3=0.f;
    #pragma unroll
    for (int i=0;i<8;i++){
        const int j  = idx_sh[nl*Mm + m0 + i];
        const int jc = (j < 0) ? 0 : j;
        const ull* Gp = (const ull*)(SGb + (size_t)jc*512) + tx*4;
        ulonglong2 g01 = *(const ulonglong2*)Gp;
        ulonglong2 g23 = *((const ulonglong2*)Gp + 1);
        ull v0 = add2(add2(acc[i][0], sp0), g01.x);
        ull v1 = add2(add2(acc[i][1], sp1), g01.y);
        ull v2 = add2(add2(acc[i][2], sp2), g23.x);
        ull v3 = add2(add2(acc[i][3], sp3), g23.y);
        float f,c;
        const float msk = (j >= 0) ? 1.f : 0.f;
        unpack2(v0,f,c); part0 += msk*sigm(f)*softplusf(c);
        unpack2(v1,f,c); part1 += msk*sigm(f)*softplusf(c);
        unpack2(v2,f,c); part2 += msk*sigm(f)*softplusf(c);
        unpack2(v3,f,c); part3 += msk*sigm(f)*softplusf(c);
    }
    const float tt0 = part0 + __shfl_xor_sync(0xFFFFFFFFu, part0, 16);
    const float tt1 = part1 + __shfl_xor_sync(0xFFFFFFFFu, part1, 16);
    const float tt2 = part2 + __shfl_xor_sync(0xFFFFFFFFu, part2, 16);
    const float tt3 = part3 + __shfl_xor_sync(0xFFFFFFFFu, part3, 16);
    if ((ty & 1) == 0){
        const float alpha = alphap[0];
        const size_t off = (size_t)node*NF + H*64 + tx*4;
        const float4 sv = *(const float4*)(nf_in + off);
        float4 o4;
        o4.x = softplusf(fmaf(alpha, sv.x, tt0));
        o4.y = softplusf(fmaf(alpha, sv.y, tt1));
        o4.z = softplusf(fmaf(alpha, sv.z, tt2));
        o4.w = softplusf(fmaf(alpha, sv.w, tt3));
        *(float4*)(nf_out + off) = o4;
    }
}

// ---------------- final linear ----------------
template<int IN,int OUT,int RPB>
__global__ void linear_kernel(const float* __restrict__ X, const float* __restrict__ W,
                              const float* __restrict__ bias, float* __restrict__ Y){
    __shared__ float Wsh[IN*(OUT+1)];
    __shared__ __align__(16) float Xsh[IN*RPB];
    const int rb = blockIdx.x * RPB;
    const int t  = threadIdx.x;
    for (int e = t; e < IN*OUT; e += OUT){
        int o = e / IN, k = e - o*IN;
        Wsh[k*(OUT+1) + o] = W[e];
    }
    for (int e = t; e < RPB*IN; e += OUT){
        int r = e / IN, k = e - r*IN;
        Xsh[k*RPB + r] = X[(size_t)(rb+r)*IN + k];
    }
    __syncthreads();
    float acc[RPB];
    #pragma unroll
    for (int r=0;r<RPB;r++) acc[r]=0.f;
    #pragma unroll 2
    for (int k=0;k<IN;k++){
        float w = Wsh[k*(OUT+1)+t];
        const float4* xr = (const float4*)(Xsh + k*RPB);
        #pragma unroll
        for (int r4=0;r4<RPB/4;r4++){
            float4 xv = xr[r4];
            acc[4*r4+0] += xv.x*w; acc[4*r4+1] += xv.y*w;
            acc[4*r4+2] += xv.z*w; acc[4*r4+3] += xv.w*w;
        }
    }
    float bv = bias[t];
    #pragma unroll
    for (int r=0;r<RPB;r++) Y[(size_t)(rb+r)*OUT + t] = acc[r] + bv;
}

// -------- output --------
__global__ void out_kernel(float* __restrict__ out){
    __shared__ float DS[32*33];
    __shared__ float NS[32*65];
    const int t  = threadIdx.x;
    const int it = blockIdx.x;
    const int b  = blockIdx.y;
    const int i_l = t & 31;
    const int fg  = t >> 5;
    float acc[8];
    #pragma unroll
    for (int f=0;f<8;f++) acc[f]=0.f;

    for (int jt=0; jt<8; jt++){
        #pragma unroll
        for (int i=0;i<4;i++){
            int e = t + i*256; int r = e>>5; int c = e&31;
            DS[r*33+c] = g_DA[(it*32+r)*Nn + jt*32 + c];
        }
        #pragma unroll
        for (int i=0;i<8;i++){
            int e = t + i*256; int j = e>>6; int f = e&63;
            NS[j*65+f] = g_fin[(b*Nn + jt*32 + j)*EF + f];
        }
        __syncthreads();
        #pragma unroll
        for (int j=0;j<32;j++){
            float d = DS[i_l*33 + j];
            #pragma unroll
            for (int f=0;f<8;f++) acc[f] += d * NS[j*65 + fg*8 + f];
        }
        __syncthreads();
    }
    const int i = it*32 + i_l;
    float* orow = out + (size_t)(b*Nn + i)*128;
    #pragma unroll
    for (int f=0;f<8;f++) orow[64 + fg*8 + f] = acc[f];
    for (int e=t; e<32*64; e+=256){
        int r = e>>6; int f = e&63;
        out[(size_t)(b*Nn + it*32 + r)*128 + f] = g_fin[(b*Nn + it*32 + r)*EF + f];
    }
}

extern "C" void kernel_launch(void* const* d_in, const int* in_sizes, int n_in,
                              void* d_out, int out_size){
    const float* node_fea = (const float*)d_in[0];
    const float* edge_fea = (const float*)d_in[1];
    const int*   eidx     = (const int*)  d_in[2];
    const float* dis      = (const float*)d_in[3];
    const float* Wn  = (const float*)d_in[4];
    const float* bn  = (const float*)d_in[5];
    const float* We  = (const float*)d_in[6];
    const float* be  = (const float*)d_in[7];
    const float* W1  = (const float*)d_in[8];
    const float* b1  = (const float*)d_in[9];
    const float* a1  = (const float*)d_in[10];
    const float* W2  = (const float*)d_in[11];
    const float* b2  = (const float*)d_in[12];
    const float* a2  = (const float*)d_in[13];
    const float* W3  = (const float*)d_in[14];
    const float* b3  = (const float*)d_in[15];
    const float* a3  = (const float*)d_in[16];
    const float* Wf  = (const float*)d_in[17];
    const float* bf  = (const float*)d_in[18];
    const float* DAw = (const float*)d_in[19];
    const float* DAb = (const float*)d_in[20];
    float* out = (float*)d_out;

    float *nfA, *nfB, *bceP, *finP, *efpP;
    ull *WceTP;
    cudaGetSymbolAddress((void**)&nfA,   g_nfA);
    cudaGetSymbolAddress((void**)&nfB,   g_nfB);
    cudaGetSymbolAddress((void**)&bceP,  g_bce);
    cudaGetSymbolAddress((void**)&WceTP, g_WceT);
    cudaGetSymbolAddress((void**)&finP,  g_fin);
    cudaGetSymbolAddress((void**)&efpP,  g_efp);

    cudaFuncSetAttribute(conv_kernel,
                         cudaFuncAttributeMaxDynamicSharedMemorySize, CONV_SMEM);

    const float* Ws[3] = {W1,W2,W3};
    const float* bs[3] = {b1,b2,b3};
    const float* as[3] = {a1,a2,a3};

    // launches: pre(1), wce2(2), sg1(3), conv1(4 = profiled)
    pre_kernel<<<PADB + ROWS/8, 256>>>(edge_fea, node_fea, Wn, bn, nfA);
    wce2_kernel<<<dim3(128,3), 48>>>(W1, W2, W3, We, be);

    float* nin  = nfA;
    float* nout = nfB;
    for (int l=0; l<3; l++){
        sg_kernel<<<dim3(ROWS/128, 4), 256>>>(nin, Ws[l], bs[l], bceP + l*256);
        conv_kernel<<<NGRP*2, 256, CONV_SMEM>>>(nin, nout, efpP, eidx,
                                                WceTP + (size_t)l*OEF*128, as[l]);
        float* tmp = nin; nin = nout; nout = tmp;
    }

    da_kernel<<<256, 256>>>(dis, DAw, DAb);
    linear_kernel<NF,EF,16><<<ROWS/16, EF>>>(nin, Wf, bf, finP);
    out_kernel<<<dim3(8, Bn), 256>>>(out);
}

// round 16
// speedup vs baseline: 1.5465x; 1.0952x over previous
#include <cuda_runtime.h>
#include <math.h>

// R16: sg rebuilt in conv's proven single-staging shape.
//  - g_Wsg[l][k][256]: W pre-packed into (F,C) FFMA2 pairs (pair p<128 = S rows
//    (p, p+128) over k[0:128); p>=128 = G rows (p-128, p) over k[128:256)).
//  - g_bsg[l][256]: packed bias pairs (S pairs: bl+W_e-folded-be; G pairs: 0).
//  - sg: A=nf plain floats (in-register dup), B=packed ull, 128x64-pair tile,
//    K resident in 2 stages, 3 barriers (was 16), native pair-store epilogue.

#define Bn   64
#define Nn   256
#define Mm   16
#define ONF  92
#define OEF  41
#define NF   128
#define EF   64
#define ROWS (Bn*Nn)   // 16384
#define NGRP (ROWS/8)  // 2048

typedef unsigned long long ull;

// ---- scratch ----
__device__ float g_nfA[ROWS*NF];
__device__ float g_nfB[ROWS*NF];
// interleaved pairs per node (512 floats): pair p at floats [2p, 2p+1]
//  p<128: (S_F(p), S_C(p)) ; p>=128: (G_F(p-128), G_C(p-128))
__device__ float g_SG[ROWS*512];
__device__ float g_efp[NGRP*OEF*128];  // GEMM-ready: [group][k][row], exact 41 k
__device__ ull   g_WceT[3*OEF*128];    // [l][k][o] = pack(WceF[o][k], WceC[o][k])
__device__ ull   g_Wsg[3*128*256];     // [l][k][pair]
__device__ ull   g_bsg[3*256];         // packed bias pairs
__device__ float g_DA[Nn*Nn];
__device__ float g_fin[ROWS*EF];

__device__ __forceinline__ float tanh_ap(float x){
    float r; asm("tanh.approx.f32 %0, %1;" : "=f"(r) : "f"(x)); return r;
}
__device__ __forceinline__ float sigm(float x){
    return fmaf(tanh_ap(0.5f*x), 0.5f, 0.5f);
}
__device__ __forceinline__ float sigm_exact(float x){
    return __fdividef(1.f, 1.f + __expf(-x));
}
__device__ __forceinline__ float softplusf(float x){
    return fmaxf(x, 0.f) + __logf(1.f + __expf(-fabsf(x)));
}

__device__ __forceinline__ ull pack2(float lo, float hi){
    ull r; asm("mov.b64 %0, {%1, %2};" : "=l"(r) : "f"(lo), "f"(hi)); return r;
}
__device__ __forceinline__ void unpack2(ull v, float &lo, float &hi){
    asm("mov.b64 {%0, %1}, %2;" : "=f"(lo), "=f"(hi) : "l"(v));
}
__device__ __forceinline__ void fma2(ull &d, ull a, ull b){
    asm("fma.rn.f32x2 %0, %1, %2, %0;" : "+l"(d) : "l"(a), "l"(b));
}
__device__ __forceinline__ ull add2(ull a, ull b){
    ull r; asm("add.rn.f32x2 %0, %1, %2;" : "=l"(r) : "l"(a), "l"(b)); return r;
}

// ======== fused pre: ef transpose (exact 41k) + embed linear ========
#define PADB ((NGRP*OEF*128)/256)    // 41984
__global__ void pre_kernel(const float* __restrict__ ef,
                           const float* __restrict__ X, const float* __restrict__ W,
                           const float* __restrict__ bias, float* __restrict__ Y){
    __shared__ float Wsh[ONF*(NF+1)];
    __shared__ __align__(16) float Xsh[ONF*8];
    const int t = threadIdx.x;
    if (blockIdx.x < PADB){
        int i = blockIdx.x*256 + t;
        int group = i / (OEF*128);
        int rem   = i - group*(OEF*128);
        int k = rem >> 7, r = rem & 127;
        g_efp[i] = ef[((size_t)group*128 + r)*OEF + k];
        return;
    }
    const int rb = (blockIdx.x - PADB) * 8;
    for (int e = t; e < ONF*NF; e += 256){
        int o = e / ONF, k = e - o*ONF;
        Wsh[k*(NF+1) + o] = W[e];
    }
    for (int e = t; e < 8*ONF; e += 256){
        int r = e / ONF, k = e - r*ONF;
        Xsh[k*8 + r] = X[(size_t)(rb+r)*ONF + k];
    }
    __syncthreads();
    if (t < NF){
        float acc[8];
        #pragma unroll
        for (int r=0;r<8;r++) acc[r]=0.f;
        #pragma unroll 2
        for (int k=0;k<ONF;k++){
            float w = Wsh[k*(NF+1)+t];
            const float4* xr = (const float4*)(Xsh + k*8);
            float4 x0 = xr[0], x1 = xr[1];
            acc[0]+=x0.x*w; acc[1]+=x0.y*w; acc[2]+=x0.z*w; acc[3]+=x0.w*w;
            acc[4]+=x1.x*w; acc[5]+=x1.y*w; acc[6]+=x1.z*w; acc[7]+=x1.w*w;
        }
        float bv = bias[t];
        #pragma unroll
        for (int r=0;r<8;r++) Y[(size_t)(rb+r)*NF + t] = acc[r] + bv;
    }
}

// ======== wsg: pre-pack W into FFMA2 pair form ========
// grid (256, 3) over pair p; 128 threads over k (coalesced W reads)
__global__ void wsg_kernel(const float* __restrict__ W1,const float* __restrict__ W2,
                           const float* __restrict__ W3){
    const int p = blockIdx.x;
    const int l = blockIdx.y;
    const int k = threadIdx.x;      // 0..127
    const float* W = (l==0)?W1:((l==1)?W2:W3);
    float lo, hi;
    if (p < 128){
        lo = W[(size_t)p*320 + k];
        hi = W[(size_t)(p+128)*320 + k];
    } else {
        int o = p - 128;
        lo = W[(size_t)o*320 + 128 + k];
        hi = W[(size_t)(o+128)*320 + 128 + k];
    }
    g_Wsg[((size_t)l*128 + k)*256 + p] = pack2(lo, hi);
}

// ======== bsg: packed bias pairs (S: bl + We-folded be ; G: 0) ========
__global__ void bsg_kernel(const float* __restrict__ W1,const float* __restrict__ W2,
                           const float* __restrict__ W3,const float* __restrict__ be,
                           const float* __restrict__ b1,const float* __restrict__ b2,
                           const float* __restrict__ b3){
    const int l = blockIdx.x;
    const int p = threadIdx.x;      // 0..255
    const float* W  = (l==0)?W1:((l==1)?W2:W3);
    const float* bl = (l==0)?b1:((l==1)?b2:b3);
    ull v = 0ULL;
    if (p < 128){
        float beF = 0.f, beC = 0.f;
        const float* rF = W + (size_t)p*320 + 256;
        const float* rC = W + (size_t)(p+128)*320 + 256;
        for (int e=0;e<EF;e++){ beF += rF[e]*be[e]; beC += rC[e]*be[e]; }
        v = pack2(bl[p] + beF, bl[p+128] + beC);
    }
    g_bsg[l*256 + p] = v;
}

// ======== wce2: g_WceT[l][k][o] only ========
__global__ void wce2_kernel(const float* __restrict__ W1,const float* __restrict__ W2,
                            const float* __restrict__ W3,const float* __restrict__ We){
    const int o = blockIdx.x;       // 0..127
    const int l = blockIdx.y;       // 0..2
    const int t = threadIdx.x;      // 0..47
    if (t >= OEF) return;
    const float* W = (l==0)?W1:((l==1)?W2:W3);
    const float* rF = W + (size_t)o*320 + 256;
    const float* rC = W + (size_t)(o+128)*320 + 256;
    float aF = 0.f, aC = 0.f;
    for (int e=0;e<EF;e++){
        float v = We[e*OEF + t];
        aF += rF[e]*v; aC += rC[e]*v;
    }
    g_WceT[(l*OEF + t)*128 + o] = pack2(aF, aC);
}

__global__ void da_kernel(const float* __restrict__ dis,
                          const float* __restrict__ wp, const float* __restrict__ bp){
    int i = blockIdx.x*256 + threadIdx.x;
    g_DA[i] = sigm_exact(wp[0]*dis[i] + bp[0]);
}

// ======== sg v16: conv-shaped. 128 rows x 64 pairs, K=128 in 2 stages ========
#define SG_SMEM (64*128*4 + 64*64*8)   // 32KB A + 32KB B = 64KB
__global__ __launch_bounds__(256,2)
void sg_kernel(const float* __restrict__ nf, const ull* __restrict__ Wsg,
               const ull* __restrict__ bsg){
    extern __shared__ __align__(16) char smembuf[];
    float* A_sh = (float*)smembuf;          // [64k][128 rows]
    ull*   B_sh = (ull*)(A_sh + 64*128);    // [64k][64 pairs]
    const int t  = threadIdx.x;
    const int tx = t & 15;                  // 4 pairs
    const int ty = t >> 4;                  // 8 rows
    const int rb = blockIdx.x * 128;
    const int cb = blockIdx.y * 64;

    // staging map for A: 2 threads per row, 32 k each
    const int sr   = t >> 1;                // 0..127
    const int half = t & 1;

    ull acc[8][4];
    #pragma unroll
    for (int i=0;i<8;i++)
        #pragma unroll
        for (int q=0;q<4;q++) acc[i][q] = 0ULL;

    #pragma unroll 1
    for (int s=0;s<2;s++){
        const int k0 = s*64;
        if (s) __syncthreads();             // drain previous compute
        // stage A [64k][128r]
        {
            const float* Arow = nf + (size_t)(rb + sr)*NF + k0 + half*32;
            #pragma unroll
            for (int q=0;q<8;q++){
                float4 v = *(const float4*)(Arow + q*4);
                const int kk = half*32 + q*4;
                A_sh[(kk+0)*128 + sr] = v.x;
                A_sh[(kk+1)*128 + sr] = v.y;
                A_sh[(kk+2)*128 + sr] = v.z;
                A_sh[(kk+3)*128 + sr] = v.w;
            }
        }
        // stage B [64k][64p]
        {
            const ull* src = Wsg + (size_t)k0*256;
            #pragma unroll
            for (int p=0;p<16;p++){
                int e = t + p*256;          // 4096
                int k = e >> 6, op = e & 63;
                B_sh[e] = src[(size_t)k*256 + cb + op];
            }
        }
        __syncthreads();
        #pragma unroll 4
        for (int k=0;k<64;k++){
            const float* Ak = A_sh + k*128 + ty*8;
            const ull*   Bk = B_sh + k*64 + tx*4;
            float4 af0 = *(const float4*)Ak;
            float4 af1 = *(const float4*)(Ak+4);
            ulonglong2 b01 = *(const ulonglong2*)Bk;
            ulonglong2 b23 = *(const ulonglong2*)(Bk+2);
            ull a0 = pack2(af0.x, af0.x);
            ull a1 = pack2(af0.y, af0.y);
            ull a2 = pack2(af0.z, af0.z);
            ull a3 = pack2(af0.w, af0.w);
            ull a4 = pack2(af1.x, af1.x);
            ull a5 = pack2(af1.y, af1.y);
            ull a6 = pack2(af1.z, af1.z);
            ull a7 = pack2(af1.w, af1.w);
            fma2(acc[0][0],a0,b01.x); fma2(acc[0][1],a0,b01.y);
            fma2(acc[0][2],a0,b23.x); fma2(acc[0][3],a0,b23.y);
            fma2(acc[1][0],a1,b01.x); fma2(acc[1][1],a1,b01.y);
            fma2(acc[1][2],a1,b23.x); fma2(acc[1][3],a1,b23.y);
            fma2(acc[2][0],a2,b01.x); fma2(acc[2][1],a2,b01.y);
            fma2(acc[2][2],a2,b23.x); fma2(acc[2][3],a2,b23.y);
            fma2(acc[3][0],a3,b01.x); fma2(acc[3][1],a3,b01.y);
            fma2(acc[3][2],a3,b23.x); fma2(acc[3][3],a3,b23.y);
            fma2(acc[4][0],a4,b01.x); fma2(acc[4][1],a4,b01.y);
            fma2(acc[4][2],a4,b23.x); fma2(acc[4][3],a4,b23.y);
            fma2(acc[5][0],a5,b01.x); fma2(acc[5][1],a5,b01.y);
            fma2(acc[5][2],a5,b23.x); fma2(acc[5][3],a5,b23.y);
            fma2(acc[6][0],a6,b01.x); fma2(acc[6][1],a6,b01.y);
            fma2(acc[6][2],a6,b23.x); fma2(acc[6][3],a6,b23.y);
            fma2(acc[7][0],a7,b01.x); fma2(acc[7][1],a7,b01.y);
            fma2(acc[7][2],a7,b23.x); fma2(acc[7][3],a7,b23.y);
        }
    }

    // epilogue: add packed bias, store pairs natively
    ulonglong2 bp01 = *(const ulonglong2*)(bsg + cb + tx*4);
    ulonglong2 bp23 = *(const ulonglong2*)(bsg + cb + tx*4 + 2);
    #pragma unroll
    for (int r=0;r<8;r++){
        const int row = rb + ty*8 + r;
        float* dst = g_SG + (size_t)row*512 + 2*(cb + tx*4);
        ulonglong2 v01, v23;
        v01.x = add2(acc[r][0], bp01.x);
        v01.y = add2(acc[r][1], bp01.y);
        v23.x = add2(acc[r][2], bp23.x);
        v23.y = add2(acc[r][3], bp23.y);
        *(ulonglong2*)dst       = v01;
        *(ulonglong2*)(dst + 4) = v23;
    }
}

// ======== conv (R15, unchanged) ========
#define CONV_SMEM (OEF*128*4 + OEF*64*8 + 8*64*8 + 128*4)
__global__ __launch_bounds__(256,2)
void conv_kernel(const float* __restrict__ nf_in, float* __restrict__ nf_out,
                 const float* __restrict__ efpT, const int* __restrict__ eidx,
                 const ull* __restrict__ WceT, const float* __restrict__ alphap){
    extern __shared__ __align__(16) char smembuf[];
    float* A_sh  = (float*)smembuf;
    ull*  B_sh   = (ull*)(A_sh + OEF*128);
    ull*  sPp_sh = B_sh + OEF*64;
    int*  idx_sh = (int*)(sPp_sh + 8*64);
    const int t  = threadIdx.x;
    const int tx = t & 15;
    const int ty = t >> 4;
    const int group = blockIdx.x >> 1;
    const int H = blockIdx.x & 1;
    const int node0 = group * 8;

    {
        const uint4* src = (const uint4*)(efpT + (size_t)group*(OEF*128));
        uint4* dst = (uint4*)A_sh;
        #pragma unroll
        for (int p=0;p<6;p++){
            int e = t + p*256;
            if (e < (OEF*128)/4) dst[e] = src[e];
        }
    }
    {
        #pragma unroll
        for (int p=0;p<11;p++){
            int e = t + p*256;
            if (e < OEF*64){
                int k = e >> 6, op = e & 63;
                B_sh[e] = WceT[k*128 + H*64 + op];
            }
        }
    }
    {
        #pragma unroll
        for (int p=0;p<2;p++){
            int e = t + p*256;
            int nl = e >> 6, op = e & 63;
            sPp_sh[e] = *(const ull*)(g_SG + (size_t)(node0+nl)*512 + 2*(H*64+op));
        }
    }
    if (t < 128) idx_sh[t] = eidx[node0*Mm + t];
    __syncthreads();

    ull acc[8][4];
    #pragma unroll
    for (int i=0;i<8;i++)
        #pragma unroll
        for (int q=0;q<4;q++) acc[i][q] = 0ULL;

    #pragma unroll 4
    for (int k=0;k<OEF;k++){
        const float* Ak = A_sh + k*128 + ty*8;
        const ull*   Bk = B_sh + k*64 + tx*4;
        float4 af0 = *(const float4*)Ak;
        float4 af1 = *(const float4*)(Ak+4);
        ulonglong2 b01 = *(const ulonglong2*)Bk;
        ulonglong2 b23 = *(const ulonglong2*)(Bk+2);
        ull a0 = pack2(af0.x, af0.x);
        ull a1 = pack2(af0.y, af0.y);
        ull a2 = pack2(af0.z, af0.z);
        ull a3 = pack2(af0.w, af0.w);
        ull a4 = pack2(af1.x, af1.x);
        ull a5 = pack2(af1.y, af1.y);
        ull a6 = pack2(af1.z, af1.z);
        ull a7 = pack2(af1.w, af1.w);
        fma2(acc[0][0],a0,b01.x); fma2(acc[0][1],a0,b01.y);
        fma2(acc[0][2],a0,b23.x); fma2(acc[0][3],a0,b23.y);
        fma2(acc[1][0],a1,b01.x); fma2(acc[1][1],a1,b01.y);
        fma2(acc[1][2],a1,b23.x); fma2(acc[1][3],a1,b23.y);
        fma2(acc[2][0],a2,b01.x); fma2(acc[2][1],a2,b01.y);
        fma2(acc[2][2],a2,b23.x); fma2(acc[2][3],a2,b23.y);
        fma2(acc[3][0],a3,b01.x); fma2(acc[3][1],a3,b01.y);
        fma2(acc[3][2],a3,b23.x); fma2(acc[3][3],a3,b23.y);
        fma2(acc[4][0],a4,b01.x); fma2(acc[4][1],a4,b01.y);
        fma2(acc[4][2],a4,b23.x); fma2(acc[4][3],a4,b23.y);
        fma2(acc[5][0],a5,b01.x); fma2(acc[5][1],a5,b01.y);
        fma2(acc[5][2],a5,b23.x); fma2(acc[5][3],a5,b23.y);
        fma2(acc[6][0],a6,b01.x); fma2(acc[6][1],a6,b01.y);
        fma2(acc[6][2],a6,b23.x); fma2(acc[6][3],a6,b23.y);
        fma2(acc[7][0],a7,b01.x); fma2(acc[7][1],a7,b01.y);
        fma2(acc[7][2],a7,b23.x); fma2(acc[7][3],a7,b23.y);
    }

    const int nl   = ty >> 1;
    const int node = node0 + nl;
    const int m0   = (ty & 1) * 8;
    const int bb   = node >> 8;
    const float* SGb = g_SG + (size_t)bb*Nn*512 + 256 + 2*(H*64);
    const ull sp0 = sPp_sh[nl*64 + tx*4 + 0];
    const ull sp1 = sPp_sh[nl*64 + tx*4 + 1];
    const ull sp2 = sPp_sh[nl*64 + tx*4 + 2];
    const ull sp3 = sPp_sh[nl*64 + tx*4 + 3];
    float part0=0.f, part1=0.f, part2=0.f, part3=0.f;
    #pragma unroll
    for (int i=0;i<8;i++){
        const int j  = idx_sh[nl*Mm + m0 + i];
        const int jc = (j < 0) ? 0 : j;
        const ull* Gp = (const ull*)(SGb + (size_t)jc*512) + tx*4;
        ulonglong2 g01 = *(const ulonglong2*)Gp;
        ulonglong2 g23 = *((const ulonglong2*)Gp + 1);
        ull v0 = add2(add2(acc[i][0], sp0), g01.x);
        ull v1 = add2(add2(acc[i][1], sp1), g01.y);
        ull v2 = add2(add2(acc[i][2], sp2), g23.x);
        ull v3 = add2(add2(acc[i][3], sp3), g23.y);
        float f,c;
        const float msk = (j >= 0) ? 1.f : 0.f;
        unpack2(v0,f,c); part0 += msk*sigm(f)*softplusf(c);
        unpack2(v1,f,c); part1 += msk*sigm(f)*softplusf(c);
        unpack2(v2,f,c); part2 += msk*sigm(f)*softplusf(c);
        unpack2(v3,f,c); part3 += msk*sigm(f)*softplusf(c);
    }
    const float tt0 = part0 + __shfl_xor_sync(0xFFFFFFFFu, part0, 16);
    const float tt1 = part1 + __shfl_xor_sync(0xFFFFFFFFu, part1, 16);
    const float tt2 = part2 + __shfl_xor_sync(0xFFFFFFFFu, part2, 16);
    const float tt3 = part3 + __shfl_xor_sync(0xFFFFFFFFu, part3, 16);
    if ((ty & 1) == 0){
        const float alpha = alphap[0];
        const size_t off = (size_t)node*NF + H*64 + tx*4;
        const float4 sv = *(const float4*)(nf_in + off);
        float4 o4;
        o4.x = softplusf(fmaf(alpha, sv.x, tt0));
        o4.y = softplusf(fmaf(alpha, sv.y, tt1));
        o4.z = softplusf(fmaf(alpha, sv.z, tt2));
        o4.w = softplusf(fmaf(alpha, sv.w, tt3));
        *(float4*)(nf_out + off) = o4;
    }
}

// ---------------- final linear ----------------
template<int IN,int OUT,int RPB>
__global__ void linear_kernel(const float* __restrict__ X, const float* __restrict__ W,
                              const float* __restrict__ bias, float* __restrict__ Y){
    __shared__ float Wsh[IN*(OUT+1)];
    __shared__ __align__(16) float Xsh[IN*RPB];
    const int rb = blockIdx.x * RPB;
    const int t  = threadIdx.x;
    for (int e = t; e < IN*OUT; e += OUT){
        int o = e / IN, k = e - o*IN;
        Wsh[k*(OUT+1) + o] = W[e];
    }
    for (int e = t; e < RPB*IN; e += OUT){
        int r = e / IN, k = e - r*IN;
        Xsh[k*RPB + r] = X[(size_t)(rb+r)*IN + k];
    }
    __syncthreads();
    float acc[RPB];
    #pragma unroll
    for (int r=0;r<RPB;r++) acc[r]=0.f;
    #pragma unroll 2
    for (int k=0;k<IN;k++){
        float w = Wsh[k*(OUT+1)+t];
        const float4* xr = (const float4*)(Xsh + k*RPB);
        #pragma unroll
        for (int r4=0;r4<RPB/4;r4++){
            float4 xv = xr[r4];
            acc[4*r4+0] += xv.x*w; acc[4*r4+1] += xv.y*w;
            acc[4*r4+2] += xv.z*w; acc[4*r4+3] += xv.w*w;
        }
    }
    float bv = bias[t];
    #pragma unroll
    for (int r=0;r<RPB;r++) Y[(size_t)(rb+r)*OUT + t] = acc[r] + bv;
}

// -------- output --------
__global__ void out_kernel(float* __restrict__ out){
    __shared__ float DS[32*33];
    __shared__ float NS[32*65];
    const int t  = threadIdx.x;
    const int it = blockIdx.x;
    const int b  = blockIdx.y;
    const int i_l = t & 31;
    const int fg  = t >> 5;
    float acc[8];
    #pragma unroll
    for (int f=0;f<8;f++) acc[f]=0.f;

    for (int jt=0; jt<8; jt++){
        #pragma unroll
        for (int i=0;i<4;i++){
            int e = t + i*256; int r = e>>5; int c = e&31;
            DS[r*33+c] = g_DA[(it*32+r)*Nn + jt*32 + c];
        }
        #pragma unroll
        for (int i=0;i<8;i++){
            int e = t + i*256; int j = e>>6; int f = e&63;
            NS[j*65+f] = g_fin[(b*Nn + jt*32 + j)*EF + f];
        }
        __syncthreads();
        #pragma unroll
        for (int j=0;j<32;j++){
            float d = DS[i_l*33 + j];
            #pragma unroll
            for (int f=0;f<8;f++) acc[f] += d * NS[j*65 + fg*8 + f];
        }
        __syncthreads();
    }
    const int i = it*32 + i_l;
    float* orow = out + (size_t)(b*Nn + i)*128;
    #pragma unroll
    for (int f=0;f<8;f++) orow[64 + fg*8 + f] = acc[f];
    for (int e=t; e<32*64; e+=256){
        int r = e>>6; int f = e&63;
        out[(size_t)(b*Nn + it*32 + r)*128 + f] = g_fin[(b*Nn + it*32 + r)*EF + f];
    }
}

extern "C" void kernel_launch(void* const* d_in, const int* in_sizes, int n_in,
                              void* d_out, int out_size){
    const float* node_fea = (const float*)d_in[0];
    const float* edge_fea = (const float*)d_in[1];
    const int*   eidx     = (const int*)  d_in[2];
    const float* dis      = (const float*)d_in[3];
    const float* Wn  = (const float*)d_in[4];
    const float* bn  = (const float*)d_in[5];
    const float* We  = (const float*)d_in[6];
    const float* be  = (const float*)d_in[7];
    const float* W1  = (const float*)d_in[8];
    const float* b1  = (const float*)d_in[9];
    const float* a1  = (const float*)d_in[10];
    const float* W2  = (const float*)d_in[11];
    const float* b2  = (const float*)d_in[12];
    const float* a2  = (const float*)d_in[13];
    const float* W3  = (const float*)d_in[14];
    const float* b3  = (const float*)d_in[15];
    const float* a3  = (const float*)d_in[16];
    const float* Wf  = (const float*)d_in[17];
    const float* bf  = (const float*)d_in[18];
    const float* DAw = (const float*)d_in[19];
    const float* DAb = (const float*)d_in[20];
    float* out = (float*)d_out;

    float *nfA, *nfB, *finP, *efpP;
    ull *WceTP, *WsgP, *bsgP;
    cudaGetSymbolAddress((void**)&nfA,   g_nfA);
    cudaGetSymbolAddress((void**)&nfB,   g_nfB);
    cudaGetSymbolAddress((void**)&WceTP, g_WceT);
    cudaGetSymbolAddress((void**)&WsgP,  g_Wsg);
    cudaGetSymbolAddress((void**)&bsgP,  g_bsg);
    cudaGetSymbolAddress((void**)&finP,  g_fin);
    cudaGetSymbolAddress((void**)&efpP,  g_efp);

    cudaFuncSetAttribute(conv_kernel,
                         cudaFuncAttributeMaxDynamicSharedMemorySize, CONV_SMEM);
    cudaFuncSetAttribute(sg_kernel,
                         cudaFuncAttributeMaxDynamicSharedMemorySize, SG_SMEM);

    const float* Ws[3] = {W1,W2,W3};
    const float* as[3] = {a1,a2,a3};

    // order: pre(1), wsg(2), bsg(3), sg1(4 = profiled), wce2(5), conv1(6), ...
    pre_kernel<<<PADB + ROWS/8, 256>>>(edge_fea, node_fea, Wn, bn, nfA);
    wsg_kernel<<<dim3(256,3), 128>>>(W1, W2, W3);
    bsg_kernel<<<3, 256>>>(W1, W2, W3, be, b1, b2, b3);

    float* nin  = nfA;
    float* nout = nfB;
    for (int l=0; l<3; l++){
        sg_kernel<<<dim3(ROWS/128, 4), 256, SG_SMEM>>>(nin,
                    WsgP + (size_t)l*128*256, bsgP + l*256);
        if (l == 0)
            wce2_kernel<<<dim3(128,3), 48>>>(W1, W2, W3, We);
        conv_kernel<<<NGRP*2, 256, CONV_SMEM>>>(nin, nout, efpP, eidx,
                                                WceTP + (size_t)l*OEF*128, as[l]);
        float* tmp = nin; nin = nout; nout = tmp;
    }

    da_kernel<<<256, 256>>>(dis, DAw, DAb);
    linear_kernel<NF,EF,16><<<ROWS/16, EF>>>(nin, Wf, bf, finP);
    out_kernel<<<dim3(8, Bn), 256>>>(out);
}

// round 17
// speedup vs baseline: 1.6790x; 1.0857x over previous
#include <cuda_runtime.h>
#include <math.h>

// R17 = R16 + ef transpose split into a smem-tiled, fully-coalesced kernel
// (efp_kernel) placed at the profiled launch slot. Embed linear standalone.

#define Bn   64
#define Nn   256
#define Mm   16
#define ONF  92
#define OEF  41
#define NF   128
#define EF   64
#define ROWS (Bn*Nn)   // 16384
#define NGRP (ROWS/8)  // 2048

typedef unsigned long long ull;

// ---- scratch ----
__device__ float g_nfA[ROWS*NF];
__device__ float g_nfB[ROWS*NF];
// interleaved pairs per node (512 floats): pair p at floats [2p, 2p+1]
__device__ float g_SG[ROWS*512];
__device__ float g_efp[NGRP*OEF*128];  // [group][k][row]
__device__ ull   g_WceT[3*OEF*128];    // [l][k][o]
__device__ ull   g_Wsg[3*128*256];     // [l][k][pair]
__device__ ull   g_bsg[3*256];
__device__ float g_DA[Nn*Nn];
__device__ float g_fin[ROWS*EF];

__device__ __forceinline__ float tanh_ap(float x){
    float r; asm("tanh.approx.f32 %0, %1;" : "=f"(r) : "f"(x)); return r;
}
__device__ __forceinline__ float sigm(float x){
    return fmaf(tanh_ap(0.5f*x), 0.5f, 0.5f);
}
__device__ __forceinline__ float sigm_exact(float x){
    return __fdividef(1.f, 1.f + __expf(-x));
}
__device__ __forceinline__ float softplusf(float x){
    return fmaxf(x, 0.f) + __logf(1.f + __expf(-fabsf(x)));
}

__device__ __forceinline__ ull pack2(float lo, float hi){
    ull r; asm("mov.b64 %0, {%1, %2};" : "=l"(r) : "f"(lo), "f"(hi)); return r;
}
__device__ __forceinline__ void unpack2(ull v, float &lo, float &hi){
    asm("mov.b64 {%0, %1}, %2;" : "=f"(lo), "=f"(hi) : "l"(v));
}
__device__ __forceinline__ void fma2(ull &d, ull a, ull b){
    asm("fma.rn.f32x2 %0, %1, %2, %0;" : "+l"(d) : "l"(a), "l"(b));
}
__device__ __forceinline__ ull add2(ull a, ull b){
    ull r; asm("add.rn.f32x2 %0, %1, %2;" : "=l"(r) : "l"(a), "l"(b)); return r;
}

// ======== embed linear (standalone) ========
__global__ void embed_kernel(const float* __restrict__ X, const float* __restrict__ W,
                             const float* __restrict__ bias, float* __restrict__ Y){
    __shared__ float Wsh[ONF*(NF+1)];
    __shared__ __align__(16) float Xsh[ONF*8];
    const int t = threadIdx.x;
    const int rb = blockIdx.x * 8;
    for (int e = t; e < ONF*NF; e += 256){
        int o = e / ONF, k = e - o*ONF;
        Wsh[k*(NF+1) + o] = W[e];
    }
    for (int e = t; e < 8*ONF; e += 256){
        int r = e / ONF, k = e - r*ONF;
        Xsh[k*8 + r] = X[(size_t)(rb+r)*ONF + k];
    }
    __syncthreads();
    if (t < NF){
        float acc[8];
        #pragma unroll
        for (int r=0;r<8;r++) acc[r]=0.f;
        #pragma unroll 2
        for (int k=0;k<ONF;k++){
            float w = Wsh[k*(NF+1)+t];
            const float4* xr = (const float4*)(Xsh + k*8);
            float4 x0 = xr[0], x1 = xr[1];
            acc[0]+=x0.x*w; acc[1]+=x0.y*w; acc[2]+=x0.z*w; acc[3]+=x0.w*w;
            acc[4]+=x1.x*w; acc[5]+=x1.y*w; acc[6]+=x1.z*w; acc[7]+=x1.w*w;
        }
        float bv = bias[t];
        #pragma unroll
        for (int r=0;r<8;r++) Y[(size_t)(rb+r)*NF + t] = acc[r] + bv;
    }
}

// ======== efp: smem-tiled transpose, coalesced in and out ========
__global__ void efp_kernel(const float* __restrict__ ef){
    __shared__ float sh[OEF*129];
    const int g = blockIdx.x;
    const int t = threadIdx.x;
    const float* src = ef + (size_t)g*128*OEF;
    for (int e = t; e < 128*OEF; e += 256){
        int r = e / OEF, k = e - r*OEF;
        sh[k*129 + r] = src[e];
    }
    __syncthreads();
    float* dst = g_efp + (size_t)g*OEF*128;
    for (int e = t; e < OEF*128; e += 256){
        int k = e >> 7, r = e & 127;
        dst[e] = sh[k*129 + r];
    }
}

// ======== wsg: pre-pack W into FFMA2 pair form ========
__global__ void wsg_kernel(const float* __restrict__ W1,const float* __restrict__ W2,
                           const float* __restrict__ W3){
    const int p = blockIdx.x;
    const int l = blockIdx.y;
    const int k = threadIdx.x;      // 0..127
    const float* W = (l==0)?W1:((l==1)?W2:W3);
    float lo, hi;
    if (p < 128){
        lo = W[(size_t)p*320 + k];
        hi = W[(size_t)(p+128)*320 + k];
    } else {
        int o = p - 128;
        lo = W[(size_t)o*320 + 128 + k];
        hi = W[(size_t)(o+128)*320 + 128 + k];
    }
    g_Wsg[((size_t)l*128 + k)*256 + p] = pack2(lo, hi);
}

// ======== bsg ========
__global__ void bsg_kernel(const float* __restrict__ W1,const float* __restrict__ W2,
                           const float* __restrict__ W3,const float* __restrict__ be,
                           const float* __restrict__ b1,const float* __restrict__ b2,
                           const float* __restrict__ b3){
    const int l = blockIdx.x;
    const int p = threadIdx.x;
    const float* W  = (l==0)?W1:((l==1)?W2:W3);
    const float* bl = (l==0)?b1:((l==1)?b2:b3);
    ull v = 0ULL;
    if (p < 128){
        float beF = 0.f, beC = 0.f;
        const float* rF = W + (size_t)p*320 + 256;
        const float* rC = W + (size_t)(p+128)*320 + 256;
        for (int e=0;e<EF;e++){ beF += rF[e]*be[e]; beC += rC[e]*be[e]; }
        v = pack2(bl[p] + beF, bl[p+128] + beC);
    }
    g_bsg[l*256 + p] = v;
}

// ======== wce2 ========
__global__ void wce2_kernel(const float* __restrict__ W1,const float* __restrict__ W2,
                            const float* __restrict__ W3,const float* __restrict__ We){
    const int o = blockIdx.x;
    const int l = blockIdx.y;
    const int t = threadIdx.x;
    if (t >= OEF) return;
    const float* W = (l==0)?W1:((l==1)?W2:W3);
    const float* rF = W + (size_t)o*320 + 256;
    const float* rC = W + (size_t)(o+128)*320 + 256;
    float aF = 0.f, aC = 0.f;
    for (int e=0;e<EF;e++){
        float v = We[e*OEF + t];
        aF += rF[e]*v; aC += rC[e]*v;
    }
    g_WceT[(l*OEF + t)*128 + o] = pack2(aF, aC);
}

__global__ void da_kernel(const float* __restrict__ dis,
                          const float* __restrict__ wp, const float* __restrict__ bp){
    int i = blockIdx.x*256 + threadIdx.x;
    g_DA[i] = sigm_exact(wp[0]*dis[i] + bp[0]);
}

// ======== sg (R16, unchanged) ========
#define SG_SMEM (64*128*4 + 64*64*8)
__global__ __launch_bounds__(256,2)
void sg_kernel(const float* __restrict__ nf, const ull* __restrict__ Wsg,
               const ull* __restrict__ bsg){
    extern __shared__ __align__(16) char smembuf[];
    float* A_sh = (float*)smembuf;
    ull*   B_sh = (ull*)(A_sh + 64*128);
    const int t  = threadIdx.x;
    const int tx = t & 15;
    const int ty = t >> 4;
    const int rb = blockIdx.x * 128;
    const int cb = blockIdx.y * 64;

    const int sr   = t >> 1;
    const int half = t & 1;

    ull acc[8][4];
    #pragma unroll
    for (int i=0;i<8;i++)
        #pragma unroll
        for (int q=0;q<4;q++) acc[i][q] = 0ULL;

    #pragma unroll 1
    for (int s=0;s<2;s++){
        const int k0 = s*64;
        if (s) __syncthreads();
        {
            const float* Arow = nf + (size_t)(rb + sr)*NF + k0 + half*32;
            #pragma unroll
            for (int q=0;q<8;q++){
                float4 v = *(const float4*)(Arow + q*4);
                const int kk = half*32 + q*4;
                A_sh[(kk+0)*128 + sr] = v.x;
                A_sh[(kk+1)*128 + sr] = v.y;
                A_sh[(kk+2)*128 + sr] = v.z;
                A_sh[(kk+3)*128 + sr] = v.w;
            }
        }
        {
            const ull* src = Wsg + (size_t)k0*256;
            #pragma unroll
            for (int p=0;p<16;p++){
                int e = t + p*256;
                int k = e >> 6, op = e & 63;
                B_sh[e] = src[(size_t)k*256 + cb + op];
            }
        }
        __syncthreads();
        #pragma unroll 4
        for (int k=0;k<64;k++){
            const float* Ak = A_sh + k*128 + ty*8;
            const ull*   Bk = B_sh + k*64 + tx*4;
            float4 af0 = *(const float4*)Ak;
            float4 af1 = *(const float4*)(Ak+4);
            ulonglong2 b01 = *(const ulonglong2*)Bk;
            ulonglong2 b23 = *(const ulonglong2*)(Bk+2);
            ull a0 = pack2(af0.x, af0.x);
            ull a1 = pack2(af0.y, af0.y);
            ull a2 = pack2(af0.z, af0.z);
            ull a3 = pack2(af0.w, af0.w);
            ull a4 = pack2(af1.x, af1.x);
            ull a5 = pack2(af1.y, af1.y);
            ull a6 = pack2(af1.z, af1.z);
            ull a7 = pack2(af1.w, af1.w);
            fma2(acc[0][0],a0,b01.x); fma2(acc[0][1],a0,b01.y);
            fma2(acc[0][2],a0,b23.x); fma2(acc[0][3],a0,b23.y);
            fma2(acc[1][0],a1,b01.x); fma2(acc[1][1],a1,b01.y);
            fma2(acc[1][2],a1,b23.x); fma2(acc[1][3],a1,b23.y);
            fma2(acc[2][0],a2,b01.x); fma2(acc[2][1],a2,b01.y);
            fma2(acc[2][2],a2,b23.x); fma2(acc[2][3],a2,b23.y);
            fma2(acc[3][0],a3,b01.x); fma2(acc[3][1],a3,b01.y);
            fma2(acc[3][2],a3,b23.x); fma2(acc[3][3],a3,b23.y);
            fma2(acc[4][0],a4,b01.x); fma2(acc[4][1],a4,b01.y);
            fma2(acc[4][2],a4,b23.x); fma2(acc[4][3],a4,b23.y);
            fma2(acc[5][0],a5,b01.x); fma2(acc[5][1],a5,b01.y);
            fma2(acc[5][2],a5,b23.x); fma2(acc[5][3],a5,b23.y);
            fma2(acc[6][0],a6,b01.x); fma2(acc[6][1],a6,b01.y);
            fma2(acc[6][2],a6,b23.x); fma2(acc[6][3],a6,b23.y);
            fma2(acc[7][0],a7,b01.x); fma2(acc[7][1],a7,b01.y);
            fma2(acc[7][2],a7,b23.x); fma2(acc[7][3],a7,b23.y);
        }
    }

    ulonglong2 bp01 = *(const ulonglong2*)(bsg + cb + tx*4);
    ulonglong2 bp23 = *(const ulonglong2*)(bsg + cb + tx*4 + 2);
    #pragma unroll
    for (int r=0;r<8;r++){
        const int row = rb + ty*8 + r;
        float* dst = g_SG + (size_t)row*512 + 2*(cb + tx*4);
        ulonglong2 v01, v23;
        v01.x = add2(acc[r][0], bp01.x);
        v01.y = add2(acc[r][1], bp01.y);
        v23.x = add2(acc[r][2], bp23.x);
        v23.y = add2(acc[r][3], bp23.y);
        *(ulonglong2*)dst       = v01;
        *(ulonglong2*)(dst + 4) = v23;
    }
}

// ======== conv (R15, unchanged) ========
#define CONV_SMEM (OEF*128*4 + OEF*64*8 + 8*64*8 + 128*4)
__global__ __launch_bounds__(256,2)
void conv_kernel(const float* __restrict__ nf_in, float* __restrict__ nf_out,
                 const float* __restrict__ efpT, const int* __restrict__ eidx,
                 const ull* __restrict__ WceT, const float* __restrict__ alphap){
    extern __shared__ __align__(16) char smembuf[];
    float* A_sh  = (float*)smembuf;
    ull*  B_sh   = (ull*)(A_sh + OEF*128);
    ull*  sPp_sh = B_sh + OEF*64;
    int*  idx_sh = (int*)(sPp_sh + 8*64);
    const int t  = threadIdx.x;
    const int tx = t & 15;
    const int ty = t >> 4;
    const int group = blockIdx.x >> 1;
    const int H = blockIdx.x & 1;
    const int node0 = group * 8;

    {
        const uint4* src = (const uint4*)(efpT + (size_t)group*(OEF*128));
        uint4* dst = (uint4*)A_sh;
        #pragma unroll
        for (int p=0;p<6;p++){
            int e = t + p*256;
            if (e < (OEF*128)/4) dst[e] = src[e];
        }
    }
    {
        #pragma unroll
        for (int p=0;p<11;p++){
            int e = t + p*256;
            if (e < OEF*64){
                int k = e >> 6, op = e & 63;
                B_sh[e] = WceT[k*128 + H*64 + op];
            }
        }
    }
    {
        #pragma unroll
        for (int p=0;p<2;p++){
            int e = t + p*256;
            int nl = e >> 6, op = e & 63;
            sPp_sh[e] = *(const ull*)(g_SG + (size_t)(node0+nl)*512 + 2*(H*64+op));
        }
    }
    if (t < 128) idx_sh[t] = eidx[node0*Mm + t];
    __syncthreads();

    ull acc[8][4];
    #pragma unroll
    for (int i=0;i<8;i++)
        #pragma unroll
        for (int q=0;q<4;q++) acc[i][q] = 0ULL;

    #pragma unroll 4
    for (int k=0;k<OEF;k++){
        const float* Ak = A_sh + k*128 + ty*8;
        const ull*   Bk = B_sh + k*64 + tx*4;
        float4 af0 = *(const float4*)Ak;
        float4 af1 = *(const float4*)(Ak+4);
        ulonglong2 b01 = *(const ulonglong2*)Bk;
        ulonglong2 b23 = *(const ulonglong2*)(Bk+2);
        ull a0 = pack2(af0.x, af0.x);
        ull a1 = pack2(af0.y, af0.y);
        ull a2 = pack2(af0.z, af0.z);
        ull a3 = pack2(af0.w, af0.w);
        ull a4 = pack2(af1.x, af1.x);
        ull a5 = pack2(af1.y, af1.y);
        ull a6 = pack2(af1.z, af1.z);
        ull a7 = pack2(af1.w, af1.w);
        fma2(acc[0][0],a0,b01.x); fma2(acc[0][1],a0,b01.y);
        fma2(acc[0][2],a0,b23.x); fma2(acc[0][3],a0,b23.y);
        fma2(acc[1][0],a1,b01.x); fma2(acc[1][1],a1,b01.y);
        fma2(acc[1][2],a1,b23.x); fma2(acc[1][3],a1,b23.y);
        fma2(acc[2][0],a2,b01.x); fma2(acc[2][1],a2,b01.y);
        fma2(acc[2][2],a2,b23.x); fma2(acc[2][3],a2,b23.y);
        fma2(acc[3][0],a3,b01.x); fma2(acc[3][1],a3,b01.y);
        fma2(acc[3][2],a3,b23.x); fma2(acc[3][3],a3,b23.y);
        fma2(acc[4][0],a4,b01.x); fma2(acc[4][1],a4,b01.y);
        fma2(acc[4][2],a4,b23.x); fma2(acc[4][3],a4,b23.y);
        fma2(acc[5][0],a5,b01.x); fma2(acc[5][1],a5,b01.y);
        fma2(acc[5][2],a5,b23.x); fma2(acc[5][3],a5,b23.y);
        fma2(acc[6][0],a6,b01.x); fma2(acc[6][1],a6,b01.y);
        fma2(acc[6][2],a6,b23.x); fma2(acc[6][3],a6,b23.y);
        fma2(acc[7][0],a7,b01.x); fma2(acc[7][1],a7,b01.y);
        fma2(acc[7][2],a7,b23.x); fma2(acc[7][3],a7,b23.y);
    }

    const int nl   = ty >> 1;
    const int node = node0 + nl;
    const int m0   = (ty & 1) * 8;
    const int bb   = node >> 8;
    const float* SGb = g_SG + (size_t)bb*Nn*512 + 256 + 2*(H*64);
    const ull sp0 = sPp_sh[nl*64 + tx*4 + 0];
    const ull sp1 = sPp_sh[nl*64 + tx*4 + 1];
    const ull sp2 = sPp_sh[nl*64 + tx*4 + 2];
    const ull sp3 = sPp_sh[nl*64 + tx*4 + 3];
    float part0=0.f, part1=0.f, part2=0.f, part3=0.f;
    #pragma unroll
    for (int i=0;i<8;i++){
        const int j  = idx_sh[nl*Mm + m0 + i];
        const int jc = (j < 0) ? 0 : j;
        const ull* Gp = (const ull*)(SGb + (size_t)jc*512) + tx*4;
        ulonglong2 g01 = *(const ulonglong2*)Gp;
        ulonglong2 g23 = *((const ulonglong2*)Gp + 1);
        ull v0 = add2(add2(acc[i][0], sp0), g01.x);
        ull v1 = add2(add2(acc[i][1], sp1), g01.y);
        ull v2 = add2(add2(acc[i][2], sp2), g23.x);
        ull v3 = add2(add2(acc[i][3], sp3), g23.y);
        float f,c;
        const float msk = (j >= 0) ? 1.f : 0.f;
        unpack2(v0,f,c); part0 += msk*sigm(f)*softplusf(c);
        unpack2(v1,f,c); part1 += msk*sigm(f)*softplusf(c);
        unpack2(v2,f,c); part2 += msk*sigm(f)*softplusf(c);
        unpack2(v3,f,c); part3 += msk*sigm(f)*softplusf(c);
    }
    const float tt0 = part0 + __shfl_xor_sync(0xFFFFFFFFu, part0, 16);
    const float tt1 = part1 + __shfl_xor_sync(0xFFFFFFFFu, part1, 16);
    const float tt2 = part2 + __shfl_xor_sync(0xFFFFFFFFu, part2, 16);
    const float tt3 = part3 + __shfl_xor_sync(0xFFFFFFFFu, part3, 16);
    if ((ty & 1) == 0){
        const float alpha = alphap[0];
        const size_t off = (size_t)node*NF + H*64 + tx*4;
        const float4 sv = *(const float4*)(nf_in + off);
        float4 o4;
        o4.x = softplusf(fmaf(alpha, sv.x, tt0));
        o4.y = softplusf(fmaf(alpha, sv.y, tt1));
        o4.z = softplusf(fmaf(alpha, sv.z, tt2));
        o4.w = softplusf(fmaf(alpha, sv.w, tt3));
        *(float4*)(nf_out + off) = o4;
    }
}

// ---------------- final linear ----------------
template<int IN,int OUT,int RPB>
__global__ void linear_kernel(const float* __restrict__ X, const float* __restrict__ W,
                              const float* __restrict__ bias, float* __restrict__ Y){
    __shared__ float Wsh[IN*(OUT+1)];
    __shared__ __align__(16) float Xsh[IN*RPB];
    const int rb = blockIdx.x * RPB;
    const int t  = threadIdx.x;
    for (int e = t; e < IN*OUT; e += OUT){
        int o = e / IN, k = e - o*IN;
        Wsh[k*(OUT+1) + o] = W[e];
    }
    for (int e = t; e < RPB*IN; e += OUT){
        int r = e / IN, k = e - r*IN;
        Xsh[k*RPB + r] = X[(size_t)(rb+r)*IN + k];
    }
    __syncthreads();
    float acc[RPB];
    #pragma unroll
    for (int r=0;r<RPB;r++) acc[r]=0.f;
    #pragma unroll 2
    for (int k=0;k<IN;k++){
        float w = Wsh[k*(OUT+1)+t];
        const float4* xr = (const float4*)(Xsh + k*RPB);
        #pragma unroll
        for (int r4=0;r4<RPB/4;r4++){
            float4 xv = xr[r4];
            acc[4*r4+0] += xv.x*w; acc[4*r4+1] += xv.y*w;
            acc[4*r4+2] += xv.z*w; acc[4*r4+3] += xv.w*w;
        }
    }
    float bv = bias[t];
    #pragma unroll
    for (int r=0;r<RPB;r++) Y[(size_t)(rb+r)*OUT + t] = acc[r] + bv;
}

// -------- output --------
__global__ void out_kernel(float* __restrict__ out){
    __shared__ float DS[32*33];
    __shared__ float NS[32*65];
    const int t  = threadIdx.x;
    const int it = blockIdx.x;
    const int b  = blockIdx.y;
    const int i_l = t & 31;
    const int fg  = t >> 5;
    float acc[8];
    #pragma unroll
    for (int f=0;f<8;f++) acc[f]=0.f;

    for (int jt=0; jt<8; jt++){
        #pragma unroll
        for (int i=0;i<4;i++){
            int e = t + i*256; int r = e>>5; int c = e&31;
            DS[r*33+c] = g_DA[(it*32+r)*Nn + jt*32 + c];
        }
        #pragma unroll
        for (int i=0;i<8;i++){
            int e = t + i*256; int j = e>>6; int f = e&63;
            NS[j*65+f] = g_fin[(b*Nn + jt*32 + j)*EF + f];
        }
        __syncthreads();
        #pragma unroll
        for (int j=0;j<32;j++){
            float d = DS[i_l*33 + j];
            #pragma unroll
            for (int f=0;f<8;f++) acc[f] += d * NS[j*65 + fg*8 + f];
        }
        __syncthreads();
    }
    const int i = it*32 + i_l;
    float* orow = out + (size_t)(b*Nn + i)*128;
    #pragma unroll
    for (int f=0;f<8;f++) orow[64 + fg*8 + f] = acc[f];
    for (int e=t; e<32*64; e+=256){
        int r = e>>6; int f = e&63;
        out[(size_t)(b*Nn + it*32 + r)*128 + f] = g_fin[(b*Nn + it*32 + r)*EF + f];
    }
}

extern "C" void kernel_launch(void* const* d_in, const int* in_sizes, int n_in,
                              void* d_out, int out_size){
    const float* node_fea = (const float*)d_in[0];
    const float* edge_fea = (const float*)d_in[1];
    const int*   eidx     = (const int*)  d_in[2];
    const float* dis      = (const float*)d_in[3];
    const float* Wn  = (const float*)d_in[4];
    const float* bn  = (const float*)d_in[5];
    const float* We  = (const float*)d_in[6];
    const float* be  = (const float*)d_in[7];
    const float* W1  = (const float*)d_in[8];
    const float* b1  = (const float*)d_in[9];
    const float* a1  = (const float*)d_in[10];
    const float* W2  = (const float*)d_in[11];
    const float* b2  = (const float*)d_in[12];
    const float* a2  = (const float*)d_in[13];
    const float* W3  = (const float*)d_in[14];
    const float* b3  = (const float*)d_in[15];
    const float* a3  = (const float*)d_in[16];
    const float* Wf  = (const float*)d_in[17];
    const float* bf  = (const float*)d_in[18];
    const float* DAw = (const float*)d_in[19];
    const float* DAb = (const float*)d_in[20];
    float* out = (float*)d_out;

    float *nfA, *nfB, *finP, *efpP;
    ull *WceTP, *WsgP, *bsgP;
    cudaGetSymbolAddress((void**)&nfA,   g_nfA);
    cudaGetSymbolAddress((void**)&nfB,   g_nfB);
    cudaGetSymbolAddress((void**)&WceTP, g_WceT);
    cudaGetSymbolAddress((void**)&WsgP,  g_Wsg);
    cudaGetSymbolAddress((void**)&bsgP,  g_bsg);
    cudaGetSymbolAddress((void**)&finP,  g_fin);
    cudaGetSymbolAddress((void**)&efpP,  g_efp);

    cudaFuncSetAttribute(conv_kernel,
                         cudaFuncAttributeMaxDynamicSharedMemorySize, CONV_SMEM);
    cudaFuncSetAttribute(sg_kernel,
                         cudaFuncAttributeMaxDynamicSharedMemorySize, SG_SMEM);

    const float* as[3] = {a1,a2,a3};

    // order: embed(1), wsg(2), bsg(3), efp(4 = profiled), sg1(5), wce2(6), conv1(7)...
    embed_kernel<<<ROWS/8, 256>>>(node_fea, Wn, bn, nfA);
    wsg_kernel<<<dim3(256,3), 128>>>(W1, W2, W3);
    bsg_kernel<<<3, 256>>>(W1, W2, W3, be, b1, b2, b3);
    efp_kernel<<<NGRP, 256>>>(edge_fea);

    float* nin  = nfA;
    float* nout = nfB;
    for (int l=0; l<3; l++){
        sg_kernel<<<dim3(ROWS/128, 4), 256, SG_SMEM>>>(nin,
                    WsgP + (size_t)l*128*256, bsgP + l*256);
        if (l == 0)
            wce2_kernel<<<dim3(128,3), 48>>>(W1, W2, W3, We);
        conv_kernel<<<NGRP*2, 256, CONV_SMEM>>>(nin, nout, efpP, eidx,
                                                WceTP + (size_t)l*OEF*128, as[l]);
        float* tmp = nin; nin = nout; nout = tmp;
    }

    da_kernel<<<256, 256>>>(dis, DAw, DAb);
    linear_kernel<NF,EF,16><<<ROWS/16, EF>>>(nin, Wf, bf, finP);
    out_kernel<<<dim3(8, Bn), 256>>>(out);
}